// round 14
// baseline (speedup 1.0000x reference)
#include <cuda_runtime.h>
#include <math.h>
#include <float.h>
#include <stdint.h>
#include <string.h>

#define B_    8
#define S_    128
#define D_    768
#define H_    12
#define DH_   64
#define DFF_  3072
#define V_    30522
#define KB_   4
#define T_    32
#define BS_   (B_*S_)
#define BKr_  (B_*KB_)
#define GRID_ 148
#define NTILE_V 239   // ceil(30522/128)

typedef unsigned long long ull;

// ---------------- static device scratch --------------------------------------
__device__ float g_h   [BS_*D_];
__device__ float g_t0  [BS_*D_];
__device__ float g_t1  [BS_*D_];
__device__ float g_t2  [BS_*D_];
__device__ float g_ctx [BS_*D_];
__device__ float g_ffn [BS_*DFF_];
__device__ float g_Kmem[BS_*D_];
__device__ float g_Vmem[BS_*D_];
__device__ float g_mb  [BS_];

__device__ float g_c   [BKr_*D_];
__device__ float g_hd  [BKr_*D_];
__device__ float g_hd2 [BKr_*D_];
__device__ float g_part [589824];
__device__ float g_part2[589824];

__device__ float g_tm [32*NTILE_V];
__device__ float g_ts [32*NTILE_V];
__device__ float g_ttv[32*NTILE_V*4];
__device__ int   g_tti[32*NTILE_V*4];

__device__ int   g_tokens[BKr_];
__device__ float g_scores[BKr_];
__device__ int   g_beamh[T_*BKr_];
__device__ int   g_tokh [T_*BKr_];

__device__ unsigned g_bar_arrive = 0;
__device__ unsigned g_bar_epoch  = 0;

// ---------------- helpers -------------------------------------------------------
__device__ __forceinline__ ull pack2(float x) {
    float2 t = make_float2(x, x);
    ull r; memcpy(&r, &t, 8); return r;
}
__device__ __forceinline__ void fma2(ull& d, ull a, ull b) {
    asm("fma.rn.f32x2 %0, %1, %2, %0;" : "+l"(d) : "l"(a), "l"(b));
}
__device__ __forceinline__ float gelu_f(float x) {
    return 0.5f * x * (1.f + tanhf(0.7978845608028654f * (x + 0.044715f * x * x * x)));
}
// jax top-k tie-break: value desc, index asc
__device__ __forceinline__ void ins4(float v, int id, float tv[4], int ti[4]) {
    if (v < tv[3] || (v == tv[3] && id > ti[3])) return;
    int j = 3;
    while (j > 0 && (v > tv[j - 1] || (v == tv[j - 1] && id < ti[j - 1]))) {
        tv[j] = tv[j - 1]; ti[j] = ti[j - 1]; j--;
    }
    tv[j] = v; ti[j] = id;
}
__device__ __forceinline__ void lsemerge(float& m, float& s, float om, float os) {
    if (om > m) { s = s * expf(m - om) + os; m = om; }
    else        { s += os * expf(om - m); }
}
__device__ __forceinline__ void merge_shfl(float tv[4], int ti[4], int off) {
    float ov[4]; int oi[4];
    #pragma unroll
    for (int j = 0; j < 4; j++) {
        ov[j] = __shfl_xor_sync(0xffffffff, tv[j], off);
        oi[j] = __shfl_xor_sync(0xffffffff, ti[j], off);
    }
    #pragma unroll
    for (int j = 0; j < 4; j++) ins4(ov[j], oi[j], tv, ti);
}

// cp.async helpers
__device__ __forceinline__ void cp16(float* dst, const float* src) {
    unsigned s = (unsigned)__cvta_generic_to_shared(dst);
    asm volatile("cp.async.cg.shared.global [%0], [%1], 16;" :: "r"(s), "l"(src));
}
__device__ __forceinline__ void cp8(float* dst, const float* src) {
    unsigned s = (unsigned)__cvta_generic_to_shared(dst);
    asm volatile("cp.async.ca.shared.global [%0], [%1], 8;" :: "r"(s), "l"(src));
}
#define CP_COMMIT() asm volatile("cp.async.commit_group;" ::: "memory")
#define CP_WAIT0()  asm volatile("cp.async.wait_group 0;" ::: "memory")

// ---------------- grid barrier (round-9 exact) ------------------------------------
__device__ __forceinline__ void gbar(unsigned& eph) {
    __threadfence();
    __syncthreads();
    if (threadIdx.x == 0) {
        eph++;
        unsigned a = atomicAdd(&g_bar_arrive, 1u);
        if (a == GRID_ - 1) {
            atomicExch(&g_bar_arrive, 0u);
            __threadfence();
            atomicExch(&g_bar_epoch, eph);
        } else {
            while (atomicAdd(&g_bar_epoch, 0u) < eph) { __nanosleep(64); }
        }
        __threadfence();
    }
    __syncthreads();
}

// ---------------- megakernel shared-mem union ------------------------------------
struct SmSk { __align__(16) float As[2][32][36]; __align__(16) float Bs[2][32][128]; };
struct SmV  { __align__(16) float As[2][32][36]; __align__(16) float Bs[2][32][128]; };
struct SmAt { float KV[128][65]; float qs[4][64]; float sc[4][128]; };
struct SmCb { float cv[16]; int ci[16]; };
union  SmAll { SmSk sk; SmV v; SmAt at; SmCb cb; };

// ---------------- skinny gemm phase (32 x 128N tile, split-K, cp.async pipe) -----
// MODE 0: A plain(__ldcg)  MODE 1: A = emb[tok]+pos[t]  MODE 2: A = gelu(sum6 partIn)
template<int MODE>
__device__ void ph_gemm(const float* __restrict__ A, const float* __restrict__ Bm,
                        float* __restrict__ part, int N, int K, int kPer,
                        int ntile, int split,
                        const int* __restrict__ tokens, const float* __restrict__ emb,
                        const float* __restrict__ pos, int t,
                        const float* __restrict__ partIn, SmSk& sm) {
    int tid = threadIdx.x;
    int tm = tid >> 5, tn = tid & 31;
    int nBase = ntile * 128;
    int k0s = split * kPer;
    int nIter = kPer / 32;
    float acc[4][4];
    #pragma unroll
    for (int m = 0; m < 4; m++)
        #pragma unroll
        for (int j = 0; j < 4; j++) acc[m][j] = 0.f;

    int am = tid >> 3, ak = (tid & 7) * 4;
    int tok = (MODE == 1) ? __ldcg(&tokens[am]) : 0;

    auto ldA = [&](int k0) -> float4 {
        if (MODE == 1) {
            float4 e4 = *(const float4*)&emb[(size_t)tok * D_ + k0 + ak];
            float4 p4 = *(const float4*)&pos[(size_t)t * D_ + k0 + ak];
            e4.x += p4.x; e4.y += p4.y; e4.z += p4.z; e4.w += p4.w;
            return e4;
        } else if (MODE == 2) {
            float4 s4 = make_float4(0.f, 0.f, 0.f, 0.f);
            #pragma unroll
            for (int sp = 0; sp < 6; sp++) {
                float4 p4 = __ldcg((const float4*)&partIn[(size_t)sp * 32 * DFF_ + am * DFF_ + k0 + ak]);
                s4.x += p4.x; s4.y += p4.y; s4.z += p4.z; s4.w += p4.w;
            }
            return make_float4(gelu_f(s4.x), gelu_f(s4.y), gelu_f(s4.z), gelu_f(s4.w));
        } else {
            return __ldcg((const float4*)&A[(size_t)am * K + k0 + ak]);
        }
    };
    auto stA = [&](int buf, float4 v) {
        *(float4*)&sm.As[buf][am][ak] = v;
    };
    auto cpB = [&](int buf, int k0) {
        #pragma unroll
        for (int i = 0; i < 4; i++) {
            int g = i * 256 + tid;             // 1024 float4s
            int bk = g >> 5, bn4 = (g & 31) * 4;
            cp16(&sm.Bs[buf][bk][bn4], &Bm[(size_t)(k0 + bk) * N + nBase + bn4]);
        }
    };

    // prologue
    float4 aCur = ldA(k0s);
    cpB(0, k0s); CP_COMMIT();
    stA(0, aCur);
    float4 aNext;
    if (nIter > 1) aNext = ldA(k0s + 32);

    for (int it = 0; it < nIter; it++) {
        int cur = it & 1, nxt = cur ^ 1;
        int k0 = k0s + it * 32;
        CP_WAIT0();
        __syncthreads();
        if (it + 1 < nIter) {
            cpB(nxt, k0 + 32); CP_COMMIT();
            stA(nxt, aNext);
            if (it + 2 < nIter) aNext = ldA(k0 + 64);
        }
        #pragma unroll
        for (int kk = 0; kk < 32; kk++) {
            float4 b4 = *(float4*)&sm.Bs[cur][kk][tn * 4];
            #pragma unroll
            for (int m = 0; m < 4; m++) {
                float a = sm.As[cur][tm * 4 + m][kk];
                acc[m][0] += a * b4.x; acc[m][1] += a * b4.y;
                acc[m][2] += a * b4.z; acc[m][3] += a * b4.w;
            }
        }
    }
    __syncthreads();
    float* Cp = part + (size_t)split * 32 * N;
    #pragma unroll
    for (int m = 0; m < 4; m++) {
        int gm = tm * 4 + m;
        #pragma unroll
        for (int j = 0; j < 4; j++)
            Cp[(size_t)gm * N + nBase + tn * 4 + j] = acc[m][j];
    }
}

// ---------------- megakernel ------------------------------------------------------
__global__ void __launch_bounds__(256) decode_mega(
        const float* __restrict__ emb, const float* __restrict__ pos,
        const float* __restrict__ Wdq, const float* __restrict__ Wdo,
        const float* __restrict__ Wd1, const float* __restrict__ Wd2,
        const float* __restrict__ Wvoc,
        float* __restrict__ out, int out_size) {
    __shared__ SmAll sm;
    __shared__ float lnsh1[8], lnsh2[8];
    __shared__ float lnm, lnr;

    int bid = blockIdx.x, tid = threadIdx.x;
    unsigned eph = 0;
    if (tid == 0) eph = atomicAdd(&g_bar_epoch, 0u);

    if (bid == 0 && tid < BKr_) {
        g_tokens[tid] = 101;
        g_scores[tid] = ((tid & 3) == 0) ? 0.f : -1e9f;
    }
    gbar(eph);

    for (int t = 0; t < T_; t++) {
        // ---- Phase 1: qd partials = (emb[tok]+pos[t]) @ Wdq  (6 ntiles x 8 splits)
        if (bid < 48)
            ph_gemm<1>(nullptr, Wdq, g_part, D_, D_, 96, bid % 6, bid / 6,
                       g_tokens, emb, pos, t, nullptr, sm.sk);
        gbar(eph);

        // ---- Phase 2: cross-attention (96 CTAs), q = sum of 8 partials
        if (bid < 96) {
            int b = bid / H_, h = bid % H_;
            {   int k = tid >> 6, d = tid & 63;
                float v = 0.f;
                #pragma unroll
                for (int s = 0; s < 8; s++)
                    v += __ldcg(&g_part[(size_t)s * 32 * D_ + (b * KB_ + k) * D_ + h * DH_ + d]);
                sm.at.qs[k][d] = v * 0.125f;
            }
            for (int idx = tid; idx < 8192; idx += 256) {
                int s = idx >> 6, d = idx & 63;
                sm.at.KV[s][d] = g_Kmem[(size_t)(b * S_ + s) * D_ + h * DH_ + d];
            }
            __syncthreads();
            #pragma unroll
            for (int rep = 0; rep < 2; rep++) {
                int p = tid + rep * 256;
                int k = p >> 7, s2 = p & 127;
                float a = 0.f;
                #pragma unroll
                for (int d = 0; d < 64; d++) a += sm.at.qs[k][d] * sm.at.KV[s2][d];
                sm.at.sc[k][s2] = a + g_mb[b * S_ + s2];
            }
            __syncthreads();
            if (tid < 128) {
                int w = tid >> 5, lane = tid & 31;
                float v[4];
                #pragma unroll
                for (int i = 0; i < 4; i++) v[i] = sm.at.sc[w][lane + i * 32];
                float m = fmaxf(fmaxf(v[0], v[1]), fmaxf(v[2], v[3]));
                #pragma unroll
                for (int o = 16; o > 0; o >>= 1) m = fmaxf(m, __shfl_xor_sync(0xffffffff, m, o));
                float p[4], ssum = 0.f;
                #pragma unroll
                for (int i = 0; i < 4; i++) { p[i] = expf(v[i] - m); ssum += p[i]; }
                #pragma unroll
                for (int o = 16; o > 0; o >>= 1) ssum += __shfl_xor_sync(0xffffffff, ssum, o);
                float inv = 1.f / ssum;
                #pragma unroll
                for (int i = 0; i < 4; i++) sm.at.sc[w][lane + i * 32] = p[i] * inv;
            }
            __syncthreads();
            for (int idx = tid; idx < 8192; idx += 256) {
                int s = idx >> 6, d = idx & 63;
                sm.at.KV[s][d] = g_Vmem[(size_t)(b * S_ + s) * D_ + h * DH_ + d];
            }
            __syncthreads();
            {   int k = tid >> 6, d = tid & 63;
                float a = 0.f;
                #pragma unroll
                for (int s = 0; s < 128; s++) a += sm.at.sc[k][s] * sm.at.KV[s][d];
                g_c[(size_t)(b * KB_ + k) * D_ + h * DH_ + d] = a;
            }
        }
        gbar(eph);

        // ---- Phase 3: c @ Wdo partials (48 CTAs)
        if (bid < 48)
            ph_gemm<0>(g_c, Wdo, g_part, D_, D_, 96, bid % 6, bid / 6,
                       nullptr, nullptr, nullptr, 0, nullptr, sm.sk);
        gbar(eph);

        // ---- Phase 4: hd = LN(emb+pos + sum8 partials)  (32 CTAs)
        if (bid < BKr_) {
            int r = bid;
            int tok = __ldcg(&g_tokens[r]);
            float v[3];
            #pragma unroll
            for (int i = 0; i < 3; i++) {
                int d = tid + i * 256;
                float s = emb[(size_t)tok * D_ + d] + pos[(size_t)t * D_ + d];
                #pragma unroll
                for (int y = 0; y < 8; y++)
                    s += __ldcg(&g_part[(size_t)y * 32 * D_ + r * D_ + d]);
                v[i] = s;
            }
            float s = 0.f, ss = 0.f;
            #pragma unroll
            for (int i = 0; i < 3; i++) { s += v[i]; ss += v[i] * v[i]; }
            #pragma unroll
            for (int off = 16; off > 0; off >>= 1) {
                s  += __shfl_xor_sync(0xffffffff, s, off);
                ss += __shfl_xor_sync(0xffffffff, ss, off);
            }
            if ((tid & 31) == 0) { lnsh1[tid >> 5] = s; lnsh2[tid >> 5] = ss; }
            __syncthreads();
            if (tid == 0) {
                float ts = 0.f, tss = 0.f;
                #pragma unroll
                for (int i = 0; i < 8; i++) { ts += lnsh1[i]; tss += lnsh2[i]; }
                float m = ts / (float)D_;
                lnm = m; lnr = rsqrtf(tss / (float)D_ - m * m + 1e-5f);
            }
            __syncthreads();
            #pragma unroll
            for (int i = 0; i < 3; i++) {
                int d = tid + i * 256;
                g_hd[(size_t)r * D_ + d] = (v[i] - lnm) * lnr;
            }
        }
        gbar(eph);

        // ---- Phase 5: hd @ Wd1 partials (24 ntiles x 6 splits = 144 CTAs)
        if (bid < 144)
            ph_gemm<0>(g_hd, Wd1, g_part, DFF_, D_, 128, bid % 24, bid / 24,
                       nullptr, nullptr, nullptr, 0, nullptr, sm.sk);
        gbar(eph);

        // ---- Phase 6: gelu(sum6 partials) @ Wd2 partials (6 x 24 = 144 CTAs)
        if (bid < 144)
            ph_gemm<2>(nullptr, Wd2, g_part2, D_, DFF_, 128, bid % 6, bid / 6,
                       nullptr, nullptr, nullptr, 0, g_part, sm.sk);
        gbar(eph);

        // ---- Phase 7: hd2 = LN(hd + sum24 partials)  (32 CTAs)
        if (bid < BKr_) {
            int r = bid;
            float v[3];
            #pragma unroll
            for (int i = 0; i < 3; i++) {
                int d = tid + i * 256;
                float s = __ldcg(&g_hd[(size_t)r * D_ + d]);
                #pragma unroll
                for (int y = 0; y < 24; y++)
                    s += __ldcg(&g_part2[(size_t)y * 32 * D_ + r * D_ + d]);
                v[i] = s;
            }
            float s = 0.f, ss = 0.f;
            #pragma unroll
            for (int i = 0; i < 3; i++) { s += v[i]; ss += v[i] * v[i]; }
            #pragma unroll
            for (int off = 16; off > 0; off >>= 1) {
                s  += __shfl_xor_sync(0xffffffff, s, off);
                ss += __shfl_xor_sync(0xffffffff, ss, off);
            }
            if ((tid & 31) == 0) { lnsh1[tid >> 5] = s; lnsh2[tid >> 5] = ss; }
            __syncthreads();
            if (tid == 0) {
                float ts = 0.f, tss = 0.f;
                #pragma unroll
                for (int i = 0; i < 8; i++) { ts += lnsh1[i]; tss += lnsh2[i]; }
                float m = ts / (float)D_;
                lnm = m; lnr = rsqrtf(tss / (float)D_ - m * m + 1e-5f);
            }
            __syncthreads();
            #pragma unroll
            for (int i = 0; i < 3; i++) {
                int d = tid + i * 256;
                g_hd2[(size_t)r * D_ + d] = (v[i] - lnm) * lnr;
            }
        }
        gbar(eph);

        // ---- Phase 8: vocab GEMM, 128-wide tiles over all 148 CTAs, cp.async pipe
        for (int tile = bid; tile < NTILE_V; tile += GRID_) {
            int nBase = tile * 128;
            bool full = (nBase + 128) <= V_;
            int tm = tid >> 5, tn = tid & 31;
            ull acc[4][2];
            #pragma unroll
            for (int m = 0; m < 4; m++) { acc[m][0] = 0ull; acc[m][1] = 0ull; }
            int am = tid >> 3, ak = (tid & 7) * 4;

            auto ldAv = [&](int k0) -> float4 {
                return __ldcg((const float4*)&g_hd2[(size_t)am * D_ + k0 + ak]);
            };
            auto stAv = [&](int buf, float4 v) {
                *(float4*)&sm.v.As[buf][am][ak] = v;
            };
            auto cpBv = [&](int buf, int k0) {
                if (full) {
                    #pragma unroll
                    for (int i = 0; i < 8; i++) {
                        int e = i * 512 + tid * 2;     // 4096 floats as float2
                        int bk = e >> 7, bn = e & 127;
                        cp8(&sm.v.Bs[buf][bk][bn],
                            &Wvoc[(size_t)(k0 + bk) * V_ + nBase + bn]);
                    }
                } else {
                    #pragma unroll
                    for (int i = 0; i < 16; i++) {
                        int e = i * 256 + tid;
                        int bk = e >> 7, bn = e & 127;
                        int gn = nBase + bn;
                        sm.v.Bs[buf][bk][bn] =
                            (gn < V_) ? __ldcg(&Wvoc[(size_t)(k0 + bk) * V_ + gn]) : 0.f;
                    }
                }
            };

            const int nIter = D_ / 32;   // 24
            float4 aCur = ldAv(0);
            cpBv(0, 0); CP_COMMIT();
            stAv(0, aCur);
            float4 aNext = ldAv(32);

            for (int it = 0; it < nIter; it++) {
                int cur = it & 1, nxt = cur ^ 1;
                int k0 = it * 32;
                CP_WAIT0();
                __syncthreads();
                if (it + 1 < nIter) {
                    cpBv(nxt, k0 + 32); CP_COMMIT();
                    stAv(nxt, aNext);
                    if (it + 2 < nIter) aNext = ldAv(k0 + 64);
                }
                #pragma unroll
                for (int kk = 0; kk < 32; kk++) {
                    ulonglong2 u = *(const ulonglong2*)&sm.v.Bs[cur][kk][tn * 4];
                    #pragma unroll
                    for (int m = 0; m < 4; m++) {
                        ull aa = pack2(sm.v.As[cur][tm * 4 + m][kk]);
                        fma2(acc[m][0], aa, u.x);
                        fma2(acc[m][1], aa, u.y);
                    }
                }
            }
            __syncthreads();

            // per-row stats over this 128-col tile
            #pragma unroll
            for (int m = 0; m < 4; m++) {
                float vals[4]; int cols[4];
                {   float2 f; memcpy(&f, &acc[m][0], 8);
                    vals[0] = f.x; vals[1] = f.y; }
                {   float2 f; memcpy(&f, &acc[m][1], 8);
                    vals[2] = f.x; vals[3] = f.y; }
                int cb = nBase + tn * 4;
                cols[0] = cb; cols[1] = cb + 1; cols[2] = cb + 2; cols[3] = cb + 3;
                float mx = -FLT_MAX, se = 0.f;
                float tv[4] = {-FLT_MAX, -FLT_MAX, -FLT_MAX, -FLT_MAX};
                int   ti[4] = {0x7fffffff, 0x7fffffff, 0x7fffffff, 0x7fffffff};
                #pragma unroll
                for (int i = 0; i < 4; i++)
                    if (cols[i] < V_) mx = fmaxf(mx, vals[i]);
                #pragma unroll
                for (int i = 0; i < 4; i++)
                    if (cols[i] < V_) { se += expf(vals[i] - mx); ins4(vals[i], cols[i], tv, ti); }
                #pragma unroll
                for (int off = 16; off > 0; off >>= 1) {
                    float om = __shfl_xor_sync(0xffffffff, mx, off);
                    float os = __shfl_xor_sync(0xffffffff, se, off);
                    lsemerge(mx, se, om, os);
                    merge_shfl(tv, ti, off);
                }
                if (tn == 0) {
                    int r = tm * 4 + m;
                    int base = r * NTILE_V + tile;
                    g_tm[base] = mx; g_ts[base] = se;
                    #pragma unroll
                    for (int j = 0; j < 4; j++) { g_ttv[base * 4 + j] = tv[j]; g_tti[base * 4 + j] = ti[j]; }
                }
            }
        }
        gbar(eph);

        // ---- Phase 9: combine tiles -> lse + per-row top4 -> beam update (8 CTAs)
        if (bid < B_) {
            int b = bid;
            if (tid < 128) {
                int k = tid >> 5, lane = tid & 31;
                int r = b * KB_ + k;
                float mx = -FLT_MAX, se = 0.f;
                float tv[4] = {-FLT_MAX, -FLT_MAX, -FLT_MAX, -FLT_MAX};
                int   ti[4] = {0x7fffffff, 0x7fffffff, 0x7fffffff, 0x7fffffff};
                for (int tile = lane; tile < NTILE_V; tile += 32) {
                    int base = r * NTILE_V + tile;
                    lsemerge(mx, se, __ldcg(&g_tm[base]), __ldcg(&g_ts[base]));
                    #pragma unroll
                    for (int j = 0; j < 4; j++)
                        ins4(__ldcg(&g_ttv[base * 4 + j]), __ldcg(&g_tti[base * 4 + j]), tv, ti);
                }
                #pragma unroll
                for (int off = 16; off > 0; off >>= 1) {
                    float om = __shfl_xor_sync(0xffffffff, mx, off);
                    float os = __shfl_xor_sync(0xffffffff, se, off);
                    lsemerge(mx, se, om, os);
                    merge_shfl(tv, ti, off);
                }
                if (lane == 0) {
                    float lse_r = mx + logf(se);
                    float base_sc = __ldcg(&g_scores[r]) - lse_r;
                    #pragma unroll
                    for (int j = 0; j < 4; j++) {
                        sm.cb.cv[k * 4 + j] = base_sc + tv[j];
                        sm.cb.ci[k * 4 + j] = k * V_ + ti[j];
                    }
                }
            }
            __syncthreads();
            if (tid == 0) {
                float tv[4] = {-FLT_MAX, -FLT_MAX, -FLT_MAX, -FLT_MAX};
                int   ti[4] = {0x7fffffff, 0x7fffffff, 0x7fffffff, 0x7fffffff};
                #pragma unroll
                for (int i = 0; i < 16; i++) ins4(sm.cb.cv[i], sm.cb.ci[i], tv, ti);
                #pragma unroll
                for (int j = 0; j < 4; j++) {
                    int id = ti[j];
                    int beam = id / V_;
                    int tok = id - beam * V_;
                    g_tokens[b * KB_ + j] = tok;
                    g_scores[b * KB_ + j] = tv[j];
                    g_tokh [t * BKr_ + b * KB_ + j] = tok;
                    g_beamh[t * BKr_ + b * KB_ + j] = beam;
                }
            }
        }
        gbar(eph);
    }

    // ---- backtrack + output
    if (bid == 0 && tid < 32) {
        int b = tid >> 2, k = tid & 3;
        int ptr = k;
        for (int t = T_ - 1; t >= 0; --t) {
            int tok = __ldcg(&g_tokh[t * BKr_ + b * KB_ + ptr]);
            int o = b * KB_ * T_ + k * T_ + t;
            if (o < out_size) out[o] = (float)tok;
            ptr = __ldcg(&g_beamh[t * BKr_ + b * KB_ + ptr]);
        }
        int o2 = B_ * KB_ * T_ + tid;
        if (o2 < out_size) out[o2] = __ldcg(&g_scores[tid]);
    }
}

// ================= encoder kernels (round-13, passing) =============================
__global__ void embed_enc_k(const int* X, const float* emb, const float* pos, float* h) {
    int r = blockIdx.x, tid = threadIdx.x;
    int tok = X[r];
    int s = r & (S_ - 1);
    #pragma unroll
    for (int i = 0; i < 3; i++) {
        int d = tid + i * 256;
        h[(size_t)r * D_ + d] = emb[(size_t)tok * D_ + d] + pos[(size_t)s * D_ + d];
    }
}

__global__ void mask_k(const int* X, float* mb) {
    int i = blockIdx.x * 256 + threadIdx.x;
    if (i < BS_) mb[i] = (X[i] != 0) ? 0.f : -1e9f;
}

__global__ void __launch_bounds__(256) sgemm128_k(
        const float* __restrict__ A, const float* __restrict__ Bm,
        float* __restrict__ C, int N, int K) {
    __shared__ __align__(16) float As[16][128];
    __shared__ __align__(16) float Bs[16][64];
    int tid = threadIdx.x;
    int tx = tid & 15, ty = tid >> 4;
    int mBase = blockIdx.y * 128, nBase = blockIdx.x * 64;
    float acc[8][4];
    #pragma unroll
    for (int i = 0; i < 8; i++)
        #pragma unroll
        for (int j = 0; j < 4; j++) acc[i][j] = 0.f;

    int am = tid >> 1, ak = (tid & 1) * 8;
    int b_k = tid >> 4, b_n = (tid & 15) * 4;

    for (int k0 = 0; k0 < K; k0 += 16) {
        float4 a0 = *(const float4*)&A[(size_t)(mBase + am) * K + k0 + ak];
        float4 a1 = *(const float4*)&A[(size_t)(mBase + am) * K + k0 + ak + 4];
        As[ak + 0][am] = a0.x; As[ak + 1][am] = a0.y;
        As[ak + 2][am] = a0.z; As[ak + 3][am] = a0.w;
        As[ak + 4][am] = a1.x; As[ak + 5][am] = a1.y;
        As[ak + 6][am] = a1.z; As[ak + 7][am] = a1.w;
        *(float4*)&Bs[b_k][b_n] = *(const float4*)&Bm[(size_t)(k0 + b_k) * N + nBase + b_n];
        __syncthreads();
        #pragma unroll
        for (int kk = 0; kk < 16; kk++) {
            float4 alo = *(const float4*)&As[kk][ty * 8];
            float4 ahi = *(const float4*)&As[kk][ty * 8 + 4];
            float4 b4  = *(const float4*)&Bs[kk][tx * 4];
            acc[0][0] += alo.x * b4.x; acc[0][1] += alo.x * b4.y; acc[0][2] += alo.x * b4.z; acc[0][3] += alo.x * b4.w;
            acc[1][0] += alo.y * b4.x; acc[1][1] += alo.y * b4.y; acc[1][2] += alo.y * b4.z; acc[1][3] += alo.y * b4.w;
            acc[2][0] += alo.z * b4.x; acc[2][1] += alo.z * b4.y; acc[2][2] += alo.z * b4.z; acc[2][3] += alo.z * b4.w;
            acc[3][0] += alo.w * b4.x; acc[3][1] += alo.w * b4.y; acc[3][2] += alo.w * b4.z; acc[3][3] += alo.w * b4.w;
            acc[4][0] += ahi.x * b4.x; acc[4][1] += ahi.x * b4.y; acc[4][2] += ahi.x * b4.z; acc[4][3] += ahi.x * b4.w;
            acc[5][0] += ahi.y * b4.x; acc[5][1] += ahi.y * b4.y; acc[5][2] += ahi.y * b4.z; acc[5][3] += ahi.y * b4.w;
            acc[6][0] += ahi.z * b4.x; acc[6][1] += ahi.z * b4.y; acc[6][2] += ahi.z * b4.z; acc[6][3] += ahi.z * b4.w;
            acc[7][0] += ahi.w * b4.x; acc[7][1] += ahi.w * b4.y; acc[7][2] += ahi.w * b4.z; acc[7][3] += ahi.w * b4.w;
        }
        __syncthreads();
    }
    #pragma unroll
    for (int i = 0; i < 8; i++) {
        int gm = mBase + ty * 8 + i;
        #pragma unroll
        for (int j = 0; j < 4; j++)
            C[(size_t)gm * N + nBase + tx * 4 + j] = acc[i][j];
    }
}

__global__ void eattn_k(const float* __restrict__ Q, const float* __restrict__ Km,
                        const float* __restrict__ Vm, const float* __restrict__ mb,
                        float* __restrict__ O) {
    __shared__ float Ks[64][64];
    __shared__ float Vs[64][64];
    int b = blockIdx.x / H_, h = blockIdx.x % H_;
    int tid = threadIdx.x;
    float q[64], acc[64];
    const float* qp = &Q[(size_t)(b * S_ + tid) * D_ + h * DH_];
    #pragma unroll
    for (int d = 0; d < 64; d++) { q[d] = qp[d] * 0.125f; acc[d] = 0.f; }
    float mrun = -3.0e38f, lrun = 0.f;

    for (int c0 = 0; c0 < S_; c0 += 64) {
        __syncthreads();
        #pragma unroll
        for (int i = 0; i < 32; i++) {
            int idx = tid + i * 128;
            int s = idx >> 6, d = idx & 63;
            Ks[s][d] = Km[(size_t)(b * S_ + c0 + s) * D_ + h * DH_ + d];
            Vs[s][d] = Vm[(size_t)(b * S_ + c0 + s) * D_ + h * DH_ + d];
        }
        __syncthreads();
        for (int j = 0; j < 64; j++) {
            float sc = mb[b * S_ + c0 + j];
            #pragma unroll
            for (int d = 0; d < 64; d++) sc += q[d] * Ks[j][d];
            float mnew = fmaxf(mrun, sc);
            float corr = expf(mrun - mnew);
            float p = expf(sc - mnew);
            lrun = lrun * corr + p;
            #pragma unroll
            for (int d = 0; d < 64; d++) acc[d] = acc[d] * corr + p * Vs[j][d];
            mrun = mnew;
        }
    }
    float inv = 1.f / lrun;
    float* op = &O[(size_t)(b * S_ + tid) * D_ + h * DH_];
    #pragma unroll
    for (int d = 0; d < 64; d++) op[d] = acc[d] * inv;
}

__global__ void addln_k(const float* __restrict__ a, const float* __restrict__ b,
                        float* __restrict__ o) {
    int r = blockIdx.x, tid = threadIdx.x;
    float v[3], s = 0.f, ss = 0.f;
    #pragma unroll
    for (int i = 0; i < 3; i++) {
        int d = tid + i * 256;
        v[i] = a[(size_t)r * D_ + d] + b[(size_t)r * D_ + d];
        s += v[i]; ss += v[i] * v[i];
    }
    __shared__ float sh1[8], sh2[8];
    __shared__ float s_mean, s_rstd;
    #pragma unroll
    for (int off = 16; off > 0; off >>= 1) {
        s  += __shfl_xor_sync(0xffffffff, s, off);
        ss += __shfl_xor_sync(0xffffffff, ss, off);
    }
    int w = tid >> 5;
    if ((tid & 31) == 0) { sh1[w] = s; sh2[w] = ss; }
    __syncthreads();
    if (tid == 0) {
        float ts = 0.f, tss = 0.f;
        #pragma unroll
        for (int i = 0; i < 8; i++) { ts += sh1[i]; tss += sh2[i]; }
        float m = ts / (float)D_;
        float var = tss / (float)D_ - m * m;
        s_mean = m; s_rstd = rsqrtf(var + 1e-5f);
    }
    __syncthreads();
    float m = s_mean, rs = s_rstd;
    #pragma unroll
    for (int i = 0; i < 3; i++) {
        int d = tid + i * 256;
        o[(size_t)r * D_ + d] = (v[i] - m) * rs;
    }
}

__global__ void gelu_k(float* x, int n) {
    int i = blockIdx.x * 256 + threadIdx.x;
    if (i < n) x[i] = gelu_f(x[i]);
}

// ================= host side ======================================================
extern "C" void kernel_launch(void* const* d_in, const int* in_sizes, int n_in,
                              void* d_out, int out_size) {
    const int*   X    = (const int*)  d_in[0];
    const float* emb  = (const float*)d_in[1];
    const float* pos  = (const float*)d_in[2];
    const float* Wq   = (const float*)d_in[3];
    const float* Wk   = (const float*)d_in[4];
    const float* Wv   = (const float*)d_in[5];
    const float* Wo   = (const float*)d_in[6];
    const float* W1   = (const float*)d_in[7];
    const float* W2   = (const float*)d_in[8];
    const float* Wdq  = (const float*)d_in[9];
    const float* Wdk  = (const float*)d_in[10];
    const float* Wdv  = (const float*)d_in[11];
    const float* Wdo  = (const float*)d_in[12];
    const float* Wd1  = (const float*)d_in[13];
    const float* Wd2  = (const float*)d_in[14];
    const float* Wvoc = (const float*)d_in[15];
    float* out = (float*)d_out;

    float *h, *t0, *t1, *t2, *ctx, *ffn, *Kmem, *Vmem, *mb;
    cudaGetSymbolAddress((void**)&h,    g_h);
    cudaGetSymbolAddress((void**)&t0,   g_t0);
    cudaGetSymbolAddress((void**)&t1,   g_t1);
    cudaGetSymbolAddress((void**)&t2,   g_t2);
    cudaGetSymbolAddress((void**)&ctx,  g_ctx);
    cudaGetSymbolAddress((void**)&ffn,  g_ffn);
    cudaGetSymbolAddress((void**)&Kmem, g_Kmem);
    cudaGetSymbolAddress((void**)&Vmem, g_Vmem);
    cudaGetSymbolAddress((void**)&mb,   g_mb);

    // ---------------- encoder (round-13) ----------------
    embed_enc_k<<<BS_, 256>>>(X, emb, pos, h);
    mask_k<<<4, 256>>>(X, mb);

    dim3 gD(D_ / 64, BS_ / 128);
    dim3 gF(DFF_ / 64, BS_ / 128);
    sgemm128_k<<<gD, 256>>>(h, Wq, t0, D_, D_);
    sgemm128_k<<<gD, 256>>>(h, Wk, t1, D_, D_);
    sgemm128_k<<<gD, 256>>>(h, Wv, t2, D_, D_);
    eattn_k<<<B_ * H_, 128>>>(t0, t1, t2, mb, ctx);
    sgemm128_k<<<gD, 256>>>(ctx, Wo, t0, D_, D_);
    addln_k<<<BS_, 256>>>(h, t0, h);
    sgemm128_k<<<gF, 256>>>(h, W1, ffn, DFF_, D_);
    gelu_k<<<(BS_ * DFF_) / 256, 256>>>(ffn, BS_ * DFF_);
    sgemm128_k<<<gD, 256>>>(ffn, W2, t0, D_, DFF_);
    addln_k<<<BS_, 256>>>(h, t0, h);
    sgemm128_k<<<gD, 256>>>(h, Wdk, Kmem, D_, D_);
    sgemm128_k<<<gD, 256>>>(h, Wdv, Vmem, D_, D_);

    // ---------------- decode: persistent megakernel ----------------
    decode_mega<<<GRID_, 256>>>(emb, pos, Wdq, Wdo, Wd1, Wd2, Wvoc, out, out_size);
}

// round 15
// speedup vs baseline: 1.1980x; 1.1980x over previous
#include <cuda_runtime.h>
#include <math.h>
#include <float.h>
#include <stdint.h>
#include <string.h>

#define B_    8
#define S_    128
#define D_    768
#define H_    12
#define DH_   64
#define DFF_  3072
#define V_    30522
#define KB_   4
#define T_    32
#define BS_   (B_*S_)
#define BKr_  (B_*KB_)
#define GRID_ 148
#define NTILE_V 120   // ceil(30522/256)

typedef unsigned long long ull;

// ---------------- static device scratch --------------------------------------
__device__ float g_h   [BS_*D_];
__device__ float g_t0  [BS_*D_];
__device__ float g_t1  [BS_*D_];
__device__ float g_t2  [BS_*D_];
__device__ float g_ctx [BS_*D_];
__device__ float g_ffn [BS_*DFF_];
__device__ float g_Kmem[BS_*D_];
__device__ float g_Vmem[BS_*D_];
__device__ float g_mb  [BS_];

__device__ float g_c   [BKr_*D_];
__device__ float g_hd  [BKr_*D_];
__device__ float g_hd2 [BKr_*D_];
__device__ float g_part [589824];
__device__ float g_part2[589824];

__device__ float g_tm [32*NTILE_V];
__device__ float g_ts [32*NTILE_V];
__device__ float g_ttv[32*NTILE_V*4];
__device__ int   g_tti[32*NTILE_V*4];

__device__ int   g_tokens[BKr_];
__device__ float g_scores[BKr_];
__device__ int   g_beamh[T_*BKr_];
__device__ int   g_tokh [T_*BKr_];

__device__ unsigned g_bar_arrive = 0;
__device__ unsigned g_bar_epoch  = 0;

// ---------------- helpers -------------------------------------------------------
__device__ __forceinline__ ull pack2(float x) {
    float2 t = make_float2(x, x);
    ull r; memcpy(&r, &t, 8); return r;
}
__device__ __forceinline__ void fma2(ull& d, ull a, ull b) {
    asm("fma.rn.f32x2 %0, %1, %2, %0;" : "+l"(d) : "l"(a), "l"(b));
}
__device__ __forceinline__ float gelu_f(float x) {
    return 0.5f * x * (1.f + tanhf(0.7978845608028654f * (x + 0.044715f * x * x * x)));
}
// jax top-k tie-break: value desc, index asc
__device__ __forceinline__ void ins4(float v, int id, float tv[4], int ti[4]) {
    if (v < tv[3] || (v == tv[3] && id > ti[3])) return;
    int j = 3;
    while (j > 0 && (v > tv[j - 1] || (v == tv[j - 1] && id < ti[j - 1]))) {
        tv[j] = tv[j - 1]; ti[j] = ti[j - 1]; j--;
    }
    tv[j] = v; ti[j] = id;
}
__device__ __forceinline__ void lsemerge(float& m, float& s, float om, float os) {
    if (om > m) { s = s * expf(m - om) + os; m = om; }
    else        { s += os * expf(om - m); }
}
__device__ __forceinline__ void merge_shfl(float tv[4], int ti[4], int off) {
    float ov[4]; int oi[4];
    #pragma unroll
    for (int j = 0; j < 4; j++) {
        ov[j] = __shfl_xor_sync(0xffffffff, tv[j], off);
        oi[j] = __shfl_xor_sync(0xffffffff, ti[j], off);
    }
    #pragma unroll
    for (int j = 0; j < 4; j++) ins4(ov[j], oi[j], tv, ti);
}

// cp.async 8B (Wvoc rows are only 8B-aligned for odd k)
__device__ __forceinline__ void cp8(float* dst, const float* src) {
    unsigned s = (unsigned)__cvta_generic_to_shared(dst);
    asm volatile("cp.async.ca.shared.global [%0], [%1], 8;" :: "r"(s), "l"(src));
}
#define CP_COMMIT() asm volatile("cp.async.commit_group;" ::: "memory")
#define CP_WAIT0()  asm volatile("cp.async.wait_group 0;" ::: "memory")

// ---------------- grid barrier (round-9 exact) ------------------------------------
__device__ __forceinline__ void gbar(unsigned& eph) {
    __threadfence();
    __syncthreads();
    if (threadIdx.x == 0) {
        eph++;
        unsigned a = atomicAdd(&g_bar_arrive, 1u);
        if (a == GRID_ - 1) {
            atomicExch(&g_bar_arrive, 0u);
            __threadfence();
            atomicExch(&g_bar_epoch, eph);
        } else {
            while (atomicAdd(&g_bar_epoch, 0u) < eph) { __nanosleep(64); }
        }
        __threadfence();
    }
    __syncthreads();
}

// ---------------- megakernel shared-mem union (DYNAMIC) ---------------------------
struct SmSk { __align__(16) float As[32][36]; __align__(16) float Bs[32][128]; };
struct SmV  { __align__(16) float As[2][32][36]; __align__(16) float Bs[2][32][256]; };
struct SmAt { float KV[128][65]; float qs[4][64]; float sc[4][128]; };
struct SmCb { float cv[16]; int ci[16]; };
union  SmAll { SmSk sk; SmV v; SmAt at; SmCb cb; };

// ---------------- skinny gemm phase (round-13 exact, synchronous) -----------------
// MODE 0: A plain(__ldcg)  MODE 1: A = emb[tok]+pos[t]  MODE 2: A = gelu(sum6 partIn)
template<int MODE>
__device__ void ph_gemm(const float* __restrict__ A, const float* __restrict__ Bm,
                        float* __restrict__ part, int N, int K, int kPer,
                        int ntile, int split,
                        const int* __restrict__ tokens, const float* __restrict__ emb,
                        const float* __restrict__ pos, int t,
                        const float* __restrict__ partIn, SmSk& sm) {
    int tid = threadIdx.x;
    int tm = tid >> 5, tn = tid & 31;
    int nBase = ntile * 128;
    int k0s = split * kPer, k0e = k0s + kPer;
    float acc[4][4];
    #pragma unroll
    for (int m = 0; m < 4; m++)
        #pragma unroll
        for (int j = 0; j < 4; j++) acc[m][j] = 0.f;

    int am = tid >> 3, ak = (tid & 7) * 4;

    for (int k0 = k0s; k0 < k0e; k0 += 32) {
        if (MODE == 1) {
            int tok = __ldcg(&tokens[am]);
            float4 e4 = *(const float4*)&emb[(size_t)tok * D_ + k0 + ak];
            float4 p4 = *(const float4*)&pos[(size_t)t * D_ + k0 + ak];
            e4.x += p4.x; e4.y += p4.y; e4.z += p4.z; e4.w += p4.w;
            *(float4*)&sm.As[am][ak] = e4;
        } else if (MODE == 2) {
            float4 s4 = make_float4(0.f, 0.f, 0.f, 0.f);
            #pragma unroll
            for (int sp = 0; sp < 6; sp++) {
                float4 p4 = __ldcg((const float4*)&partIn[(size_t)sp * 32 * DFF_ + am * DFF_ + k0 + ak]);
                s4.x += p4.x; s4.y += p4.y; s4.z += p4.z; s4.w += p4.w;
            }
            sm.As[am][ak + 0] = gelu_f(s4.x); sm.As[am][ak + 1] = gelu_f(s4.y);
            sm.As[am][ak + 2] = gelu_f(s4.z); sm.As[am][ak + 3] = gelu_f(s4.w);
        } else {
            float4 a4 = __ldcg((const float4*)&A[(size_t)am * K + k0 + ak]);
            *(float4*)&sm.As[am][ak] = a4;
        }
        #pragma unroll
        for (int i = 0; i < 8; i++) {
            int e = i * 512 + tid * 2;
            int bk = e >> 7, bn = e & 127;
            *(float2*)&sm.Bs[bk][bn] = *(const float2*)&Bm[(size_t)(k0 + bk) * N + nBase + bn];
        }
        __syncthreads();
        #pragma unroll
        for (int kk = 0; kk < 32; kk++) {
            float4 b4 = *(float4*)&sm.Bs[kk][tn * 4];
            #pragma unroll
            for (int m = 0; m < 4; m++) {
                float a = sm.As[tm * 4 + m][kk];
                acc[m][0] += a * b4.x; acc[m][1] += a * b4.y;
                acc[m][2] += a * b4.z; acc[m][3] += a * b4.w;
            }
        }
        __syncthreads();
    }
    float* Cp = part + (size_t)split * 32 * N;
    #pragma unroll
    for (int m = 0; m < 4; m++) {
        int gm = tm * 4 + m;
        #pragma unroll
        for (int j = 0; j < 4; j++)
            Cp[(size_t)gm * N + nBase + tn * 4 + j] = acc[m][j];
    }
}

// ---------------- megakernel ------------------------------------------------------
__global__ void __launch_bounds__(256) decode_mega(
        const float* __restrict__ emb, const float* __restrict__ pos,
        const float* __restrict__ Wdq, const float* __restrict__ Wdo,
        const float* __restrict__ Wd1, const float* __restrict__ Wd2,
        const float* __restrict__ Wvoc,
        float* __restrict__ out, int out_size) {
    extern __shared__ __align__(16) char smraw[];
    SmAll& sm = *reinterpret_cast<SmAll*>(smraw);
    __shared__ float lnsh1[8], lnsh2[8];
    __shared__ float lnm, lnr;

    int bid = blockIdx.x, tid = threadIdx.x;
    unsigned eph = 0;
    if (tid == 0) eph = atomicAdd(&g_bar_epoch, 0u);

    if (bid == 0 && tid < BKr_) {
        g_tokens[tid] = 101;
        g_scores[tid] = ((tid & 3) == 0) ? 0.f : -1e9f;
    }
    gbar(eph);

    for (int t = 0; t < T_; t++) {
        // ---- Phase 1: qd partials = (emb[tok]+pos[t]) @ Wdq  (6 ntiles x 8 splits)
        if (bid < 48)
            ph_gemm<1>(nullptr, Wdq, g_part, D_, D_, 96, bid % 6, bid / 6,
                       g_tokens, emb, pos, t, nullptr, sm.sk);
        gbar(eph);

        // ---- Phase 2: cross-attention (96 CTAs), q = sum of 8 partials
        if (bid < 96) {
            int b = bid / H_, h = bid % H_;
            {   int k = tid >> 6, d = tid & 63;
                float v = 0.f;
                #pragma unroll
                for (int s = 0; s < 8; s++)
                    v += __ldcg(&g_part[(size_t)s * 32 * D_ + (b * KB_ + k) * D_ + h * DH_ + d]);
                sm.at.qs[k][d] = v * 0.125f;
            }
            for (int idx = tid; idx < 8192; idx += 256) {
                int s = idx >> 6, d = idx & 63;
                sm.at.KV[s][d] = g_Kmem[(size_t)(b * S_ + s) * D_ + h * DH_ + d];
            }
            __syncthreads();
            #pragma unroll
            for (int rep = 0; rep < 2; rep++) {
                int p = tid + rep * 256;
                int k = p >> 7, s2 = p & 127;
                float a = 0.f;
                #pragma unroll
                for (int d = 0; d < 64; d++) a += sm.at.qs[k][d] * sm.at.KV[s2][d];
                sm.at.sc[k][s2] = a + g_mb[b * S_ + s2];
            }
            __syncthreads();
            if (tid < 128) {
                int w = tid >> 5, lane = tid & 31;
                float v[4];
                #pragma unroll
                for (int i = 0; i < 4; i++) v[i] = sm.at.sc[w][lane + i * 32];
                float m = fmaxf(fmaxf(v[0], v[1]), fmaxf(v[2], v[3]));
                #pragma unroll
                for (int o = 16; o > 0; o >>= 1) m = fmaxf(m, __shfl_xor_sync(0xffffffff, m, o));
                float p[4], ssum = 0.f;
                #pragma unroll
                for (int i = 0; i < 4; i++) { p[i] = expf(v[i] - m); ssum += p[i]; }
                #pragma unroll
                for (int o = 16; o > 0; o >>= 1) ssum += __shfl_xor_sync(0xffffffff, ssum, o);
                float inv = 1.f / ssum;
                #pragma unroll
                for (int i = 0; i < 4; i++) sm.at.sc[w][lane + i * 32] = p[i] * inv;
            }
            __syncthreads();
            for (int idx = tid; idx < 8192; idx += 256) {
                int s = idx >> 6, d = idx & 63;
                sm.at.KV[s][d] = g_Vmem[(size_t)(b * S_ + s) * D_ + h * DH_ + d];
            }
            __syncthreads();
            {   int k = tid >> 6, d = tid & 63;
                float a = 0.f;
                #pragma unroll
                for (int s = 0; s < 128; s++) a += sm.at.sc[k][s] * sm.at.KV[s][d];
                g_c[(size_t)(b * KB_ + k) * D_ + h * DH_ + d] = a;
            }
        }
        gbar(eph);

        // ---- Phase 3: c @ Wdo partials (48 CTAs)
        if (bid < 48)
            ph_gemm<0>(g_c, Wdo, g_part, D_, D_, 96, bid % 6, bid / 6,
                       nullptr, nullptr, nullptr, 0, nullptr, sm.sk);
        gbar(eph);

        // ---- Phase 4: hd = LN(emb+pos + sum8 partials)  (32 CTAs)
        if (bid < BKr_) {
            int r = bid;
            int tok = __ldcg(&g_tokens[r]);
            float v[3];
            #pragma unroll
            for (int i = 0; i < 3; i++) {
                int d = tid + i * 256;
                float s = emb[(size_t)tok * D_ + d] + pos[(size_t)t * D_ + d];
                #pragma unroll
                for (int y = 0; y < 8; y++)
                    s += __ldcg(&g_part[(size_t)y * 32 * D_ + r * D_ + d]);
                v[i] = s;
            }
            float s = 0.f, ss = 0.f;
            #pragma unroll
            for (int i = 0; i < 3; i++) { s += v[i]; ss += v[i] * v[i]; }
            #pragma unroll
            for (int off = 16; off > 0; off >>= 1) {
                s  += __shfl_xor_sync(0xffffffff, s, off);
                ss += __shfl_xor_sync(0xffffffff, ss, off);
            }
            if ((tid & 31) == 0) { lnsh1[tid >> 5] = s; lnsh2[tid >> 5] = ss; }
            __syncthreads();
            if (tid == 0) {
                float ts = 0.f, tss = 0.f;
                #pragma unroll
                for (int i = 0; i < 8; i++) { ts += lnsh1[i]; tss += lnsh2[i]; }
                float m = ts / (float)D_;
                lnm = m; lnr = rsqrtf(tss / (float)D_ - m * m + 1e-5f);
            }
            __syncthreads();
            #pragma unroll
            for (int i = 0; i < 3; i++) {
                int d = tid + i * 256;
                g_hd[(size_t)r * D_ + d] = (v[i] - lnm) * lnr;
            }
        }
        gbar(eph);

        // ---- Phase 5: hd @ Wd1 partials (24 ntiles x 6 splits = 144 CTAs)
        if (bid < 144)
            ph_gemm<0>(g_hd, Wd1, g_part, DFF_, D_, 128, bid % 24, bid / 24,
                       nullptr, nullptr, nullptr, 0, nullptr, sm.sk);
        gbar(eph);

        // ---- Phase 6: gelu(sum6 partials) @ Wd2 partials (6 x 24 = 144 CTAs)
        if (bid < 144)
            ph_gemm<2>(nullptr, Wd2, g_part2, D_, DFF_, 128, bid % 6, bid / 6,
                       nullptr, nullptr, nullptr, 0, g_part, sm.sk);
        gbar(eph);

        // ---- Phase 7: hd2 = LN(hd + sum24 partials)  (32 CTAs)
        if (bid < BKr_) {
            int r = bid;
            float v[3];
            #pragma unroll
            for (int i = 0; i < 3; i++) {
                int d = tid + i * 256;
                float s = __ldcg(&g_hd[(size_t)r * D_ + d]);
                #pragma unroll
                for (int y = 0; y < 24; y++)
                    s += __ldcg(&g_part2[(size_t)y * 32 * D_ + r * D_ + d]);
                v[i] = s;
            }
            float s = 0.f, ss = 0.f;
            #pragma unroll
            for (int i = 0; i < 3; i++) { s += v[i]; ss += v[i] * v[i]; }
            #pragma unroll
            for (int off = 16; off > 0; off >>= 1) {
                s  += __shfl_xor_sync(0xffffffff, s, off);
                ss += __shfl_xor_sync(0xffffffff, ss, off);
            }
            if ((tid & 31) == 0) { lnsh1[tid >> 5] = s; lnsh2[tid >> 5] = ss; }
            __syncthreads();
            if (tid == 0) {
                float ts = 0.f, tss = 0.f;
                #pragma unroll
                for (int i = 0; i < 8; i++) { ts += lnsh1[i]; tss += lnsh2[i]; }
                float m = ts / (float)D_;
                lnm = m; lnr = rsqrtf(tss / (float)D_ - m * m + 1e-5f);
            }
            __syncthreads();
            #pragma unroll
            for (int i = 0; i < 3; i++) {
                int d = tid + i * 256;
                g_hd2[(size_t)r * D_ + d] = (v[i] - lnm) * lnr;
            }
        }
        gbar(eph);

        // ---- Phase 8: vocab GEMM, 120 balanced 256-wide tiles, cp.async pipeline
        if (bid < NTILE_V) {
            int tile = bid;
            int nBase = tile * 256;
            bool full = (nBase + 256) <= V_;
            int tm = tid >> 5, tn = tid & 31;
            ull acc[4][4];
            #pragma unroll
            for (int m = 0; m < 4; m++)
                #pragma unroll
                for (int j = 0; j < 4; j++) acc[m][j] = 0ull;
            int am = tid >> 3, ak = (tid & 7) * 4;

            auto ldAv = [&](int k0) -> float4 {
                return __ldcg((const float4*)&g_hd2[(size_t)am * D_ + k0 + ak]);
            };
            auto stAv = [&](int buf, float4 v) {
                *(float4*)&sm.v.As[buf][am][ak] = v;
            };
            auto cpBv = [&](int buf, int k0) {
                if (full) {
                    #pragma unroll
                    for (int i = 0; i < 16; i++) {
                        int e = i * 512 + tid * 2;       // 8192 floats as float2
                        int bk = e >> 8, bn = e & 255;
                        cp8(&sm.v.Bs[buf][bk][bn],
                            &Wvoc[(size_t)(k0 + bk) * V_ + nBase + bn]);
                    }
                } else {
                    #pragma unroll
                    for (int i = 0; i < 32; i++) {
                        int gn = nBase + tid;
                        sm.v.Bs[buf][i][tid] =
                            (gn < V_) ? __ldcg(&Wvoc[(size_t)(k0 + i) * V_ + gn]) : 0.f;
                    }
                }
            };

            const int nIter = D_ / 32;   // 24
            float4 aCur = ldAv(0);
            cpBv(0, 0); CP_COMMIT();
            stAv(0, aCur);
            float4 aNext = ldAv(32);

            for (int it = 0; it < nIter; it++) {
                int cur = it & 1, nxt = cur ^ 1;
                int k0 = it * 32;
                CP_WAIT0();
                __syncthreads();
                if (it + 1 < nIter) {
                    cpBv(nxt, k0 + 32); CP_COMMIT();
                    stAv(nxt, aNext);
                    if (it + 2 < nIter) aNext = ldAv(k0 + 64);
                }
                #pragma unroll
                for (int kk = 0; kk < 32; kk++) {
                    ulonglong2 u0 = *(const ulonglong2*)&sm.v.Bs[cur][kk][tn * 4];
                    ulonglong2 u1 = *(const ulonglong2*)&sm.v.Bs[cur][kk][128 + tn * 4];
                    #pragma unroll
                    for (int m = 0; m < 4; m++) {
                        ull aa = pack2(sm.v.As[cur][tm * 4 + m][kk]);
                        fma2(acc[m][0], aa, u0.x);
                        fma2(acc[m][1], aa, u0.y);
                        fma2(acc[m][2], aa, u1.x);
                        fma2(acc[m][3], aa, u1.y);
                    }
                }
            }
            __syncthreads();

            // per-row stats (round-13 exact mapping)
            #pragma unroll
            for (int m = 0; m < 4; m++) {
                float vals[8]; int cols[8];
                #pragma unroll
                for (int j = 0; j < 4; j++) {
                    float2 f; memcpy(&f, &acc[m][j], 8);
                    int cb = nBase + ((j >> 1) ? 128 : 0) + tn * 4 + (j & 1) * 2;
                    vals[j * 2] = f.x;     cols[j * 2] = cb;
                    vals[j * 2 + 1] = f.y; cols[j * 2 + 1] = cb + 1;
                }
                float mx = -FLT_MAX, se = 0.f;
                float tv[4] = {-FLT_MAX, -FLT_MAX, -FLT_MAX, -FLT_MAX};
                int   ti[4] = {0x7fffffff, 0x7fffffff, 0x7fffffff, 0x7fffffff};
                #pragma unroll
                for (int i = 0; i < 8; i++)
                    if (cols[i] < V_) mx = fmaxf(mx, vals[i]);
                #pragma unroll
                for (int i = 0; i < 8; i++)
                    if (cols[i] < V_) { se += expf(vals[i] - mx); ins4(vals[i], cols[i], tv, ti); }
                #pragma unroll
                for (int off = 16; off > 0; off >>= 1) {
                    float om = __shfl_xor_sync(0xffffffff, mx, off);
                    float os = __shfl_xor_sync(0xffffffff, se, off);
                    lsemerge(mx, se, om, os);
                    merge_shfl(tv, ti, off);
                }
                if (tn == 0) {
                    int r = tm * 4 + m;
                    int base = r * NTILE_V + tile;
                    g_tm[base] = mx; g_ts[base] = se;
                    #pragma unroll
                    for (int j = 0; j < 4; j++) { g_ttv[base * 4 + j] = tv[j]; g_tti[base * 4 + j] = ti[j]; }
                }
            }
        }
        gbar(eph);

        // ---- Phase 9: combine tiles -> lse + per-row top4 -> beam update (8 CTAs)
        if (bid < B_) {
            int b = bid;
            if (tid < 128) {
                int k = tid >> 5, lane = tid & 31;
                int r = b * KB_ + k;
                float mx = -FLT_MAX, se = 0.f;
                float tv[4] = {-FLT_MAX, -FLT_MAX, -FLT_MAX, -FLT_MAX};
                int   ti[4] = {0x7fffffff, 0x7fffffff, 0x7fffffff, 0x7fffffff};
                for (int tile = lane; tile < NTILE_V; tile += 32) {
                    int base = r * NTILE_V + tile;
                    lsemerge(mx, se, __ldcg(&g_tm[base]), __ldcg(&g_ts[base]));
                    #pragma unroll
                    for (int j = 0; j < 4; j++)
                        ins4(__ldcg(&g_ttv[base * 4 + j]), __ldcg(&g_tti[base * 4 + j]), tv, ti);
                }
                #pragma unroll
                for (int off = 16; off > 0; off >>= 1) {
                    float om = __shfl_xor_sync(0xffffffff, mx, off);
                    float os = __shfl_xor_sync(0xffffffff, se, off);
                    lsemerge(mx, se, om, os);
                    merge_shfl(tv, ti, off);
                }
                if (lane == 0) {
                    float lse_r = mx + logf(se);
                    float base_sc = __ldcg(&g_scores[r]) - lse_r;
                    #pragma unroll
                    for (int j = 0; j < 4; j++) {
                        sm.cb.cv[k * 4 + j] = base_sc + tv[j];
                        sm.cb.ci[k * 4 + j] = k * V_ + ti[j];
                    }
                }
            }
            __syncthreads();
            if (tid == 0) {
                float tv[4] = {-FLT_MAX, -FLT_MAX, -FLT_MAX, -FLT_MAX};
                int   ti[4] = {0x7fffffff, 0x7fffffff, 0x7fffffff, 0x7fffffff};
                #pragma unroll
                for (int i = 0; i < 16; i++) ins4(sm.cb.cv[i], sm.cb.ci[i], tv, ti);
                #pragma unroll
                for (int j = 0; j < 4; j++) {
                    int id = ti[j];
                    int beam = id / V_;
                    int tok = id - beam * V_;
                    g_tokens[b * KB_ + j] = tok;
                    g_scores[b * KB_ + j] = tv[j];
                    g_tokh [t * BKr_ + b * KB_ + j] = tok;
                    g_beamh[t * BKr_ + b * KB_ + j] = beam;
                }
            }
        }
        gbar(eph);
    }

    // ---- backtrack + output
    if (bid == 0 && tid < 32) {
        int b = tid >> 2, k = tid & 3;
        int ptr = k;
        for (int t = T_ - 1; t >= 0; --t) {
            int tok = __ldcg(&g_tokh[t * BKr_ + b * KB_ + ptr]);
            int o = b * KB_ * T_ + k * T_ + t;
            if (o < out_size) out[o] = (float)tok;
            ptr = __ldcg(&g_beamh[t * BKr_ + b * KB_ + ptr]);
        }
        int o2 = B_ * KB_ * T_ + tid;
        if (o2 < out_size) out[o2] = __ldcg(&g_scores[tid]);
    }
}

// ================= encoder kernels (round-13, passing) =============================
__global__ void embed_enc_k(const int* X, const float* emb, const float* pos, float* h) {
    int r = blockIdx.x, tid = threadIdx.x;
    int tok = X[r];
    int s = r & (S_ - 1);
    #pragma unroll
    for (int i = 0; i < 3; i++) {
        int d = tid + i * 256;
        h[(size_t)r * D_ + d] = emb[(size_t)tok * D_ + d] + pos[(size_t)s * D_ + d];
    }
}

__global__ void mask_k(const int* X, float* mb) {
    int i = blockIdx.x * 256 + threadIdx.x;
    if (i < BS_) mb[i] = (X[i] != 0) ? 0.f : -1e9f;
}

__global__ void __launch_bounds__(256) sgemm128_k(
        const float* __restrict__ A, const float* __restrict__ Bm,
        float* __restrict__ C, int N, int K) {
    __shared__ __align__(16) float As[16][128];
    __shared__ __align__(16) float Bs[16][64];
    int tid = threadIdx.x;
    int tx = tid & 15, ty = tid >> 4;
    int mBase = blockIdx.y * 128, nBase = blockIdx.x * 64;
    float acc[8][4];
    #pragma unroll
    for (int i = 0; i < 8; i++)
        #pragma unroll
        for (int j = 0; j < 4; j++) acc[i][j] = 0.f;

    int am = tid >> 1, ak = (tid & 1) * 8;
    int b_k = tid >> 4, b_n = (tid & 15) * 4;

    for (int k0 = 0; k0 < K; k0 += 16) {
        float4 a0 = *(const float4*)&A[(size_t)(mBase + am) * K + k0 + ak];
        float4 a1 = *(const float4*)&A[(size_t)(mBase + am) * K + k0 + ak + 4];
        As[ak + 0][am] = a0.x; As[ak + 1][am] = a0.y;
        As[ak + 2][am] = a0.z; As[ak + 3][am] = a0.w;
        As[ak + 4][am] = a1.x; As[ak + 5][am] = a1.y;
        As[ak + 6][am] = a1.z; As[ak + 7][am] = a1.w;
        *(float4*)&Bs[b_k][b_n] = *(const float4*)&Bm[(size_t)(k0 + b_k) * N + nBase + b_n];
        __syncthreads();
        #pragma unroll
        for (int kk = 0; kk < 16; kk++) {
            float4 alo = *(const float4*)&As[kk][ty * 8];
            float4 ahi = *(const float4*)&As[kk][ty * 8 + 4];
            float4 b4  = *(const float4*)&Bs[kk][tx * 4];
            acc[0][0] += alo.x * b4.x; acc[0][1] += alo.x * b4.y; acc[0][2] += alo.x * b4.z; acc[0][3] += alo.x * b4.w;
            acc[1][0] += alo.y * b4.x; acc[1][1] += alo.y * b4.y; acc[1][2] += alo.y * b4.z; acc[1][3] += alo.y * b4.w;
            acc[2][0] += alo.z * b4.x; acc[2][1] += alo.z * b4.y; acc[2][2] += alo.z * b4.z; acc[2][3] += alo.z * b4.w;
            acc[3][0] += alo.w * b4.x; acc[3][1] += alo.w * b4.y; acc[3][2] += alo.w * b4.z; acc[3][3] += alo.w * b4.w;
            acc[4][0] += ahi.x * b4.x; acc[4][1] += ahi.x * b4.y; acc[4][2] += ahi.x * b4.z; acc[4][3] += ahi.x * b4.w;
            acc[5][0] += ahi.y * b4.x; acc[5][1] += ahi.y * b4.y; acc[5][2] += ahi.y * b4.z; acc[5][3] += ahi.y * b4.w;
            acc[6][0] += ahi.z * b4.x; acc[6][1] += ahi.z * b4.y; acc[6][2] += ahi.z * b4.z; acc[6][3] += ahi.z * b4.w;
            acc[7][0] += ahi.w * b4.x; acc[7][1] += ahi.w * b4.y; acc[7][2] += ahi.w * b4.z; acc[7][3] += ahi.w * b4.w;
        }
        __syncthreads();
    }
    #pragma unroll
    for (int i = 0; i < 8; i++) {
        int gm = mBase + ty * 8 + i;
        #pragma unroll
        for (int j = 0; j < 4; j++)
            C[(size_t)gm * N + nBase + tx * 4 + j] = acc[i][j];
    }
}

__global__ void eattn_k(const float* __restrict__ Q, const float* __restrict__ Km,
                        const float* __restrict__ Vm, const float* __restrict__ mb,
                        float* __restrict__ O) {
    __shared__ float Ks[64][64];
    __shared__ float Vs[64][64];
    int b = blockIdx.x / H_, h = blockIdx.x % H_;
    int tid = threadIdx.x;
    float q[64], acc[64];
    const float* qp = &Q[(size_t)(b * S_ + tid) * D_ + h * DH_];
    #pragma unroll
    for (int d = 0; d < 64; d++) { q[d] = qp[d] * 0.125f; acc[d] = 0.f; }
    float mrun = -3.0e38f, lrun = 0.f;

    for (int c0 = 0; c0 < S_; c0 += 64) {
        __syncthreads();
        #pragma unroll
        for (int i = 0; i < 32; i++) {
            int idx = tid + i * 128;
            int s = idx >> 6, d = idx & 63;
            Ks[s][d] = Km[(size_t)(b * S_ + c0 + s) * D_ + h * DH_ + d];
            Vs[s][d] = Vm[(size_t)(b * S_ + c0 + s) * D_ + h * DH_ + d];
        }
        __syncthreads();
        for (int j = 0; j < 64; j++) {
            float sc = mb[b * S_ + c0 + j];
            #pragma unroll
            for (int d = 0; d < 64; d++) sc += q[d] * Ks[j][d];
            float mnew = fmaxf(mrun, sc);
            float corr = expf(mrun - mnew);
            float p = expf(sc - mnew);
            lrun = lrun * corr + p;
            #pragma unroll
            for (int d = 0; d < 64; d++) acc[d] = acc[d] * corr + p * Vs[j][d];
            mrun = mnew;
        }
    }
    float inv = 1.f / lrun;
    float* op = &O[(size_t)(b * S_ + tid) * D_ + h * DH_];
    #pragma unroll
    for (int d = 0; d < 64; d++) op[d] = acc[d] * inv;
}

__global__ void addln_k(const float* __restrict__ a, const float* __restrict__ b,
                        float* __restrict__ o) {
    int r = blockIdx.x, tid = threadIdx.x;
    float v[3], s = 0.f, ss = 0.f;
    #pragma unroll
    for (int i = 0; i < 3; i++) {
        int d = tid + i * 256;
        v[i] = a[(size_t)r * D_ + d] + b[(size_t)r * D_ + d];
        s += v[i]; ss += v[i] * v[i];
    }
    __shared__ float sh1[8], sh2[8];
    __shared__ float s_mean, s_rstd;
    #pragma unroll
    for (int off = 16; off > 0; off >>= 1) {
        s  += __shfl_xor_sync(0xffffffff, s, off);
        ss += __shfl_xor_sync(0xffffffff, ss, off);
    }
    int w = tid >> 5;
    if ((tid & 31) == 0) { sh1[w] = s; sh2[w] = ss; }
    __syncthreads();
    if (tid == 0) {
        float ts = 0.f, tss = 0.f;
        #pragma unroll
        for (int i = 0; i < 8; i++) { ts += sh1[i]; tss += sh2[i]; }
        float m = ts / (float)D_;
        float var = tss / (float)D_ - m * m;
        s_mean = m; s_rstd = rsqrtf(var + 1e-5f);
    }
    __syncthreads();
    float m = s_mean, rs = s_rstd;
    #pragma unroll
    for (int i = 0; i < 3; i++) {
        int d = tid + i * 256;
        o[(size_t)r * D_ + d] = (v[i] - m) * rs;
    }
}

__global__ void gelu_k(float* x, int n) {
    int i = blockIdx.x * 256 + threadIdx.x;
    if (i < n) x[i] = gelu_f(x[i]);
}

// ================= host side ======================================================
extern "C" void kernel_launch(void* const* d_in, const int* in_sizes, int n_in,
                              void* d_out, int out_size) {
    const int*   X    = (const int*)  d_in[0];
    const float* emb  = (const float*)d_in[1];
    const float* pos  = (const float*)d_in[2];
    const float* Wq   = (const float*)d_in[3];
    const float* Wk   = (const float*)d_in[4];
    const float* Wv   = (const float*)d_in[5];
    const float* Wo   = (const float*)d_in[6];
    const float* W1   = (const float*)d_in[7];
    const float* W2   = (const float*)d_in[8];
    const float* Wdq  = (const float*)d_in[9];
    const float* Wdk  = (const float*)d_in[10];
    const float* Wdv  = (const float*)d_in[11];
    const float* Wdo  = (const float*)d_in[12];
    const float* Wd1  = (const float*)d_in[13];
    const float* Wd2  = (const float*)d_in[14];
    const float* Wvoc = (const float*)d_in[15];
    float* out = (float*)d_out;

    float *h, *t0, *t1, *t2, *ctx, *ffn, *Kmem, *Vmem, *mb;
    cudaGetSymbolAddress((void**)&h,    g_h);
    cudaGetSymbolAddress((void**)&t0,   g_t0);
    cudaGetSymbolAddress((void**)&t1,   g_t1);
    cudaGetSymbolAddress((void**)&t2,   g_t2);
    cudaGetSymbolAddress((void**)&ctx,  g_ctx);
    cudaGetSymbolAddress((void**)&ffn,  g_ffn);
    cudaGetSymbolAddress((void**)&Kmem, g_Kmem);
    cudaGetSymbolAddress((void**)&Vmem, g_Vmem);
    cudaGetSymbolAddress((void**)&mb,   g_mb);

    // ---------------- encoder (round-13) ----------------
    embed_enc_k<<<BS_, 256>>>(X, emb, pos, h);
    mask_k<<<4, 256>>>(X, mb);

    dim3 gD(D_ / 64, BS_ / 128);
    dim3 gF(DFF_ / 64, BS_ / 128);
    sgemm128_k<<<gD, 256>>>(h, Wq, t0, D_, D_);
    sgemm128_k<<<gD, 256>>>(h, Wk, t1, D_, D_);
    sgemm128_k<<<gD, 256>>>(h, Wv, t2, D_, D_);
    eattn_k<<<B_ * H_, 128>>>(t0, t1, t2, mb, ctx);
    sgemm128_k<<<gD, 256>>>(ctx, Wo, t0, D_, D_);
    addln_k<<<BS_, 256>>>(h, t0, h);
    sgemm128_k<<<gF, 256>>>(h, W1, ffn, DFF_, D_);
    gelu_k<<<(BS_ * DFF_) / 256, 256>>>(ffn, BS_ * DFF_);
    sgemm128_k<<<gD, 256>>>(ffn, W2, t0, D_, DFF_);
    addln_k<<<BS_, 256>>>(h, t0, h);
    sgemm128_k<<<gD, 256>>>(h, Wdk, Kmem, D_, D_);
    sgemm128_k<<<gD, 256>>>(h, Wdv, Vmem, D_, D_);

    // ---------------- decode: persistent megakernel (dynamic smem) ----------------
    static int smem_set = 0;
    int smemBytes = (int)sizeof(SmAll);
    if (!smem_set) {
        cudaFuncSetAttribute(decode_mega,
                             cudaFuncAttributeMaxDynamicSharedMemorySize, smemBytes);
        smem_set = 1;
    }
    decode_mega<<<GRID_, 256, smemBytes>>>(emb, pos, Wdq, Wdo, Wd1, Wd2, Wvoc,
                                           out, out_size);
}

// round 16
// speedup vs baseline: 1.2295x; 1.0263x over previous
#include <cuda_runtime.h>
#include <math.h>
#include <float.h>
#include <stdint.h>
#include <string.h>

#define B_    8
#define S_    128
#define D_    768
#define H_    12
#define DH_   64
#define DFF_  3072
#define V_    30522
#define KB_   4
#define T_    32
#define BS_   (B_*S_)
#define BKr_  (B_*KB_)
#define GRID_ 148
#define NTILE_V 120   // ceil(30522/256)

typedef unsigned long long ull;

// ---------------- static device scratch --------------------------------------
__device__ float g_h   [BS_*D_];
__device__ float g_t0  [BS_*D_];
__device__ float g_t1  [BS_*D_];
__device__ float g_t2  [BS_*D_];
__device__ float g_ctx [BS_*D_];
__device__ float g_ffn [BS_*DFF_];
__device__ float g_Kmem[BS_*D_];
__device__ float g_Vmem[BS_*D_];
__device__ float g_mb  [BS_];

__device__ float g_c   [BKr_*D_];
__device__ float g_hd  [BKr_*D_];
__device__ float g_hd2 [BKr_*D_];
__device__ float g_part [589824];
__device__ float g_part2[589824];

__device__ float g_tm [32*NTILE_V];
__device__ float g_ts [32*NTILE_V];
__device__ float g_ttv[32*NTILE_V*4];
__device__ int   g_tti[32*NTILE_V*4];

__device__ int   g_tokens[BKr_];
__device__ float g_scores[BKr_];
__device__ int   g_beamh[T_*BKr_];
__device__ int   g_tokh [T_*BKr_];

__device__ unsigned g_bar_arrive = 0;
__device__ unsigned g_bar_epoch  = 0;

// ---------------- helpers -------------------------------------------------------
__device__ __forceinline__ ull pack2(float x) {
    float2 t = make_float2(x, x);
    ull r; memcpy(&r, &t, 8); return r;
}
__device__ __forceinline__ void fma2(ull& d, ull a, ull b) {
    asm("fma.rn.f32x2 %0, %1, %2, %0;" : "+l"(d) : "l"(a), "l"(b));
}
__device__ __forceinline__ float gelu_f(float x) {
    return 0.5f * x * (1.f + tanhf(0.7978845608028654f * (x + 0.044715f * x * x * x)));
}
// jax top-k tie-break: value desc, index asc
__device__ __forceinline__ void ins4(float v, int id, float tv[4], int ti[4]) {
    if (v < tv[3] || (v == tv[3] && id > ti[3])) return;
    int j = 3;
    while (j > 0 && (v > tv[j - 1] || (v == tv[j - 1] && id < ti[j - 1]))) {
        tv[j] = tv[j - 1]; ti[j] = ti[j - 1]; j--;
    }
    tv[j] = v; ti[j] = id;
}
__device__ __forceinline__ void lsemerge(float& m, float& s, float om, float os) {
    if (om > m) { s = s * expf(m - om) + os; m = om; }
    else        { s += os * expf(om - m); }
}
__device__ __forceinline__ void merge_shfl(float tv[4], int ti[4], int off) {
    float ov[4]; int oi[4];
    #pragma unroll
    for (int j = 0; j < 4; j++) {
        ov[j] = __shfl_xor_sync(0xffffffff, tv[j], off);
        oi[j] = __shfl_xor_sync(0xffffffff, ti[j], off);
    }
    #pragma unroll
    for (int j = 0; j < 4; j++) ins4(ov[j], oi[j], tv, ti);
}

// cp.async helpers
__device__ __forceinline__ void cp16(float* dst, const float* src) {
    unsigned s = (unsigned)__cvta_generic_to_shared(dst);
    asm volatile("cp.async.cg.shared.global [%0], [%1], 16;" :: "r"(s), "l"(src));
}
__device__ __forceinline__ void cp8(float* dst, const float* src) {
    unsigned s = (unsigned)__cvta_generic_to_shared(dst);
    asm volatile("cp.async.ca.shared.global [%0], [%1], 8;" :: "r"(s), "l"(src));
}
#define CP_COMMIT() asm volatile("cp.async.commit_group;" ::: "memory")
#define CP_WAIT0()  asm volatile("cp.async.wait_group 0;" ::: "memory")

// ---------------- grid barrier (round-9 exact) ------------------------------------
__device__ __forceinline__ void gbar(unsigned& eph) {
    __threadfence();
    __syncthreads();
    if (threadIdx.x == 0) {
        eph++;
        unsigned a = atomicAdd(&g_bar_arrive, 1u);
        if (a == GRID_ - 1) {
            atomicExch(&g_bar_arrive, 0u);
            __threadfence();
            atomicExch(&g_bar_epoch, eph);
        } else {
            while (atomicAdd(&g_bar_epoch, 0u) < eph) { __nanosleep(64); }
        }
        __threadfence();
    }
    __syncthreads();
}

// ---------------- megakernel shared-mem union (DYNAMIC) ---------------------------
struct SmSk { __align__(16) float As[2][32][36]; __align__(16) float Bs[2][32][128]; };
struct SmV  { __align__(16) float As[2][32][36]; __align__(16) float Bs[2][32][256]; };
struct SmAt { float KV[128][65]; float qs[4][64]; float sc[4][128]; };
struct SmCb { float cv[16]; int ci[16]; };
union  SmAll { SmSk sk; SmV v; SmAt at; SmCb cb; };

// ---------------- skinny gemm phase (32 x 128N tile, split-K, cp.async pipe) -----
// MODE 0: A plain(__ldcg)  MODE 1: A = emb[tok]+pos[t]  MODE 2: A = gelu(sum6 partIn)
template<int MODE>
__device__ void ph_gemm(const float* __restrict__ A, const float* __restrict__ Bm,
                        float* __restrict__ part, int N, int K, int kPer,
                        int ntile, int split,
                        const int* __restrict__ tokens, const float* __restrict__ emb,
                        const float* __restrict__ pos, int t,
                        const float* __restrict__ partIn, SmSk& sm) {
    int tid = threadIdx.x;
    int tm = tid >> 5, tn = tid & 31;
    int nBase = ntile * 128;
    int k0s = split * kPer;
    int nIter = kPer / 32;
    float acc[4][4];
    #pragma unroll
    for (int m = 0; m < 4; m++)
        #pragma unroll
        for (int j = 0; j < 4; j++) acc[m][j] = 0.f;

    int am = tid >> 3, ak = (tid & 7) * 4;
    int tok = (MODE == 1) ? __ldcg(&tokens[am]) : 0;

    auto ldA = [&](int k0) -> float4 {
        if (MODE == 1) {
            float4 e4 = *(const float4*)&emb[(size_t)tok * D_ + k0 + ak];
            float4 p4 = *(const float4*)&pos[(size_t)t * D_ + k0 + ak];
            e4.x += p4.x; e4.y += p4.y; e4.z += p4.z; e4.w += p4.w;
            return e4;
        } else if (MODE == 2) {
            float4 s4 = make_float4(0.f, 0.f, 0.f, 0.f);
            #pragma unroll
            for (int sp = 0; sp < 6; sp++) {
                float4 p4 = __ldcg((const float4*)&partIn[(size_t)sp * 32 * DFF_ + am * DFF_ + k0 + ak]);
                s4.x += p4.x; s4.y += p4.y; s4.z += p4.z; s4.w += p4.w;
            }
            return make_float4(gelu_f(s4.x), gelu_f(s4.y), gelu_f(s4.z), gelu_f(s4.w));
        } else {
            return __ldcg((const float4*)&A[(size_t)am * K + k0 + ak]);
        }
    };
    auto stA = [&](int buf, float4 v) {
        *(float4*)&sm.As[buf][am][ak] = v;
    };
    auto cpB = [&](int buf, int k0) {
        #pragma unroll
        for (int i = 0; i < 4; i++) {
            int g = i * 256 + tid;             // 1024 float4s total
            int bk = g >> 5, bn4 = (g & 31) * 4;
            cp16(&sm.Bs[buf][bk][bn4], &Bm[(size_t)(k0 + bk) * N + nBase + bn4]);
        }
    };

    // prologue
    float4 aCur = ldA(k0s);
    cpB(0, k0s); CP_COMMIT();
    stA(0, aCur);
    float4 aNext;
    if (nIter > 1) aNext = ldA(k0s + 32);

    for (int it = 0; it < nIter; it++) {
        int cur = it & 1, nxt = cur ^ 1;
        int k0 = k0s + it * 32;
        CP_WAIT0();
        __syncthreads();
        if (it + 1 < nIter) {
            cpB(nxt, k0 + 32); CP_COMMIT();
            stA(nxt, aNext);
            if (it + 2 < nIter) aNext = ldA(k0 + 64);
        }
        #pragma unroll
        for (int kk = 0; kk < 32; kk++) {
            float4 b4 = *(float4*)&sm.Bs[cur][kk][tn * 4];
            #pragma unroll
            for (int m = 0; m < 4; m++) {
                float a = sm.As[cur][tm * 4 + m][kk];
                acc[m][0] += a * b4.x; acc[m][1] += a * b4.y;
                acc[m][2] += a * b4.z; acc[m][3] += a * b4.w;
            }
        }
    }
    __syncthreads();
    float* Cp = part + (size_t)split * 32 * N;
    #pragma unroll
    for (int m = 0; m < 4; m++) {
        int gm = tm * 4 + m;
        #pragma unroll
        for (int j = 0; j < 4; j++)
            Cp[(size_t)gm * N + nBase + tn * 4 + j] = acc[m][j];
    }
}

// ---------------- megakernel ------------------------------------------------------
__global__ void __launch_bounds__(256) decode_mega(
        const float* __restrict__ emb, const float* __restrict__ pos,
        const float* __restrict__ Wdq, const float* __restrict__ Wdo,
        const float* __restrict__ Wd1, const float* __restrict__ Wd2,
        const float* __restrict__ Wvoc,
        float* __restrict__ out, int out_size) {
    extern __shared__ __align__(16) char smraw[];
    SmAll& sm = *reinterpret_cast<SmAll*>(smraw);
    __shared__ float lnsh1[8], lnsh2[8];
    __shared__ float lnm, lnr;

    int bid = blockIdx.x, tid = threadIdx.x;
    unsigned eph = 0;
    if (tid == 0) eph = atomicAdd(&g_bar_epoch, 0u);

    if (bid == 0 && tid < BKr_) {
        g_tokens[tid] = 101;
        g_scores[tid] = ((tid & 3) == 0) ? 0.f : -1e9f;
    }
    gbar(eph);

    for (int t = 0; t < T_; t++) {
        // ---- Phase 1: qd partials = (emb[tok]+pos[t]) @ Wdq  (6 ntiles x 8 splits)
        if (bid < 48)
            ph_gemm<1>(nullptr, Wdq, g_part, D_, D_, 96, bid % 6, bid / 6,
                       g_tokens, emb, pos, t, nullptr, sm.sk);
        gbar(eph);

        // ---- Phase 2: cross-attention (96 CTAs), q = sum of 8 partials
        if (bid < 96) {
            int b = bid / H_, h = bid % H_;
            {   int k = tid >> 6, d = tid & 63;
                float v = 0.f;
                #pragma unroll
                for (int s = 0; s < 8; s++)
                    v += __ldcg(&g_part[(size_t)s * 32 * D_ + (b * KB_ + k) * D_ + h * DH_ + d]);
                sm.at.qs[k][d] = v * 0.125f;
            }
            for (int idx = tid; idx < 8192; idx += 256) {
                int s = idx >> 6, d = idx & 63;
                sm.at.KV[s][d] = g_Kmem[(size_t)(b * S_ + s) * D_ + h * DH_ + d];
            }
            __syncthreads();
            #pragma unroll
            for (int rep = 0; rep < 2; rep++) {
                int p = tid + rep * 256;
                int k = p >> 7, s2 = p & 127;
                float a = 0.f;
                #pragma unroll
                for (int d = 0; d < 64; d++) a += sm.at.qs[k][d] * sm.at.KV[s2][d];
                sm.at.sc[k][s2] = a + g_mb[b * S_ + s2];
            }
            __syncthreads();
            if (tid < 128) {
                int w = tid >> 5, lane = tid & 31;
                float v[4];
                #pragma unroll
                for (int i = 0; i < 4; i++) v[i] = sm.at.sc[w][lane + i * 32];
                float m = fmaxf(fmaxf(v[0], v[1]), fmaxf(v[2], v[3]));
                #pragma unroll
                for (int o = 16; o > 0; o >>= 1) m = fmaxf(m, __shfl_xor_sync(0xffffffff, m, o));
                float p[4], ssum = 0.f;
                #pragma unroll
                for (int i = 0; i < 4; i++) { p[i] = expf(v[i] - m); ssum += p[i]; }
                #pragma unroll
                for (int o = 16; o > 0; o >>= 1) ssum += __shfl_xor_sync(0xffffffff, ssum, o);
                float inv = 1.f / ssum;
                #pragma unroll
                for (int i = 0; i < 4; i++) sm.at.sc[w][lane + i * 32] = p[i] * inv;
            }
            __syncthreads();
            for (int idx = tid; idx < 8192; idx += 256) {
                int s = idx >> 6, d = idx & 63;
                sm.at.KV[s][d] = g_Vmem[(size_t)(b * S_ + s) * D_ + h * DH_ + d];
            }
            __syncthreads();
            {   int k = tid >> 6, d = tid & 63;
                float a = 0.f;
                #pragma unroll
                for (int s = 0; s < 128; s++) a += sm.at.sc[k][s] * sm.at.KV[s][d];
                g_c[(size_t)(b * KB_ + k) * D_ + h * DH_ + d] = a;
            }
        }
        gbar(eph);

        // ---- Phase 3: c @ Wdo partials (48 CTAs)
        if (bid < 48)
            ph_gemm<0>(g_c, Wdo, g_part, D_, D_, 96, bid % 6, bid / 6,
                       nullptr, nullptr, nullptr, 0, nullptr, sm.sk);
        gbar(eph);

        // ---- Phase 4: hd = LN(emb+pos + sum8 partials)  (32 CTAs)
        if (bid < BKr_) {
            int r = bid;
            int tok = __ldcg(&g_tokens[r]);
            float v[3];
            #pragma unroll
            for (int i = 0; i < 3; i++) {
                int d = tid + i * 256;
                float s = emb[(size_t)tok * D_ + d] + pos[(size_t)t * D_ + d];
                #pragma unroll
                for (int y = 0; y < 8; y++)
                    s += __ldcg(&g_part[(size_t)y * 32 * D_ + r * D_ + d]);
                v[i] = s;
            }
            float s = 0.f, ss = 0.f;
            #pragma unroll
            for (int i = 0; i < 3; i++) { s += v[i]; ss += v[i] * v[i]; }
            #pragma unroll
            for (int off = 16; off > 0; off >>= 1) {
                s  += __shfl_xor_sync(0xffffffff, s, off);
                ss += __shfl_xor_sync(0xffffffff, ss, off);
            }
            if ((tid & 31) == 0) { lnsh1[tid >> 5] = s; lnsh2[tid >> 5] = ss; }
            __syncthreads();
            if (tid == 0) {
                float ts = 0.f, tss = 0.f;
                #pragma unroll
                for (int i = 0; i < 8; i++) { ts += lnsh1[i]; tss += lnsh2[i]; }
                float m = ts / (float)D_;
                lnm = m; lnr = rsqrtf(tss / (float)D_ - m * m + 1e-5f);
            }
            __syncthreads();
            #pragma unroll
            for (int i = 0; i < 3; i++) {
                int d = tid + i * 256;
                g_hd[(size_t)r * D_ + d] = (v[i] - lnm) * lnr;
            }
        }
        gbar(eph);

        // ---- Phase 5: hd @ Wd1 partials (24 ntiles x 6 splits = 144 CTAs)
        if (bid < 144)
            ph_gemm<0>(g_hd, Wd1, g_part, DFF_, D_, 128, bid % 24, bid / 24,
                       nullptr, nullptr, nullptr, 0, nullptr, sm.sk);
        gbar(eph);

        // ---- Phase 6: gelu(sum6 partials) @ Wd2 partials (6 x 24 = 144 CTAs)
        if (bid < 144)
            ph_gemm<2>(nullptr, Wd2, g_part2, D_, DFF_, 128, bid % 6, bid / 6,
                       nullptr, nullptr, nullptr, 0, g_part, sm.sk);
        gbar(eph);

        // ---- Phase 7: hd2 = LN(hd + sum24 partials)  (32 CTAs)
        if (bid < BKr_) {
            int r = bid;
            float v[3];
            #pragma unroll
            for (int i = 0; i < 3; i++) {
                int d = tid + i * 256;
                float s = __ldcg(&g_hd[(size_t)r * D_ + d]);
                #pragma unroll
                for (int y = 0; y < 24; y++)
                    s += __ldcg(&g_part2[(size_t)y * 32 * D_ + r * D_ + d]);
                v[i] = s;
            }
            float s = 0.f, ss = 0.f;
            #pragma unroll
            for (int i = 0; i < 3; i++) { s += v[i]; ss += v[i] * v[i]; }
            #pragma unroll
            for (int off = 16; off > 0; off >>= 1) {
                s  += __shfl_xor_sync(0xffffffff, s, off);
                ss += __shfl_xor_sync(0xffffffff, ss, off);
            }
            if ((tid & 31) == 0) { lnsh1[tid >> 5] = s; lnsh2[tid >> 5] = ss; }
            __syncthreads();
            if (tid == 0) {
                float ts = 0.f, tss = 0.f;
                #pragma unroll
                for (int i = 0; i < 8; i++) { ts += lnsh1[i]; tss += lnsh2[i]; }
                float m = ts / (float)D_;
                lnm = m; lnr = rsqrtf(tss / (float)D_ - m * m + 1e-5f);
            }
            __syncthreads();
            #pragma unroll
            for (int i = 0; i < 3; i++) {
                int d = tid + i * 256;
                g_hd2[(size_t)r * D_ + d] = (v[i] - lnm) * lnr;
            }
        }
        gbar(eph);

        // ---- Phase 8: vocab GEMM, 120 balanced 256-wide tiles, cp.async pipeline
        if (bid < NTILE_V) {
            int tile = bid;
            int nBase = tile * 256;
            bool full = (nBase + 256) <= V_;
            int tm = tid >> 5, tn = tid & 31;
            ull acc[4][4];
            #pragma unroll
            for (int m = 0; m < 4; m++)
                #pragma unroll
                for (int j = 0; j < 4; j++) acc[m][j] = 0ull;
            int am = tid >> 3, ak = (tid & 7) * 4;

            auto ldAv = [&](int k0) -> float4 {
                return __ldcg((const float4*)&g_hd2[(size_t)am * D_ + k0 + ak]);
            };
            auto stAv = [&](int buf, float4 v) {
                *(float4*)&sm.v.As[buf][am][ak] = v;
            };
            auto cpBv = [&](int buf, int k0) {
                if (full) {
                    #pragma unroll
                    for (int i = 0; i < 16; i++) {
                        int e = i * 512 + tid * 2;
                        int bk = e >> 8, bn = e & 255;
                        cp8(&sm.v.Bs[buf][bk][bn],
                            &Wvoc[(size_t)(k0 + bk) * V_ + nBase + bn]);
                    }
                } else {
                    #pragma unroll
                    for (int i = 0; i < 32; i++) {
                        int gn = nBase + tid;
                        sm.v.Bs[buf][i][tid] =
                            (gn < V_) ? __ldcg(&Wvoc[(size_t)(k0 + i) * V_ + gn]) : 0.f;
                    }
                }
            };

            const int nIter = D_ / 32;   // 24
            float4 aCur = ldAv(0);
            cpBv(0, 0); CP_COMMIT();
            stAv(0, aCur);
            float4 aNext = ldAv(32);

            for (int it = 0; it < nIter; it++) {
                int cur = it & 1, nxt = cur ^ 1;
                int k0 = it * 32;
                CP_WAIT0();
                __syncthreads();
                if (it + 1 < nIter) {
                    cpBv(nxt, k0 + 32); CP_COMMIT();
                    stAv(nxt, aNext);
                    if (it + 2 < nIter) aNext = ldAv(k0 + 64);
                }
                #pragma unroll
                for (int kk = 0; kk < 32; kk++) {
                    ulonglong2 u0 = *(const ulonglong2*)&sm.v.Bs[cur][kk][tn * 4];
                    ulonglong2 u1 = *(const ulonglong2*)&sm.v.Bs[cur][kk][128 + tn * 4];
                    #pragma unroll
                    for (int m = 0; m < 4; m++) {
                        ull aa = pack2(sm.v.As[cur][tm * 4 + m][kk]);
                        fma2(acc[m][0], aa, u0.x);
                        fma2(acc[m][1], aa, u0.y);
                        fma2(acc[m][2], aa, u1.x);
                        fma2(acc[m][3], aa, u1.y);
                    }
                }
            }
            __syncthreads();

            // per-row stats (round-13 exact mapping)
            #pragma unroll
            for (int m = 0; m < 4; m++) {
                float vals[8]; int cols[8];
                #pragma unroll
                for (int j = 0; j < 4; j++) {
                    float2 f; memcpy(&f, &acc[m][j], 8);
                    int cb = nBase + ((j >> 1) ? 128 : 0) + tn * 4 + (j & 1) * 2;
                    vals[j * 2] = f.x;     cols[j * 2] = cb;
                    vals[j * 2 + 1] = f.y; cols[j * 2 + 1] = cb + 1;
                }
                float mx = -FLT_MAX, se = 0.f;
                float tv[4] = {-FLT_MAX, -FLT_MAX, -FLT_MAX, -FLT_MAX};
                int   ti[4] = {0x7fffffff, 0x7fffffff, 0x7fffffff, 0x7fffffff};
                #pragma unroll
                for (int i = 0; i < 8; i++)
                    if (cols[i] < V_) mx = fmaxf(mx, vals[i]);
                #pragma unroll
                for (int i = 0; i < 8; i++)
                    if (cols[i] < V_) { se += expf(vals[i] - mx); ins4(vals[i], cols[i], tv, ti); }
                #pragma unroll
                for (int off = 16; off > 0; off >>= 1) {
                    float om = __shfl_xor_sync(0xffffffff, mx, off);
                    float os = __shfl_xor_sync(0xffffffff, se, off);
                    lsemerge(mx, se, om, os);
                    merge_shfl(tv, ti, off);
                }
                if (tn == 0) {
                    int r = tm * 4 + m;
                    int base = r * NTILE_V + tile;
                    g_tm[base] = mx; g_ts[base] = se;
                    #pragma unroll
                    for (int j = 0; j < 4; j++) { g_ttv[base * 4 + j] = tv[j]; g_tti[base * 4 + j] = ti[j]; }
                }
            }
        }
        gbar(eph);

        // ---- Phase 9: combine tiles -> lse + per-row top4 -> beam update (8 CTAs)
        if (bid < B_) {
            int b = bid;
            if (tid < 128) {
                int k = tid >> 5, lane = tid & 31;
                int r = b * KB_ + k;
                float mx = -FLT_MAX, se = 0.f;
                float tv[4] = {-FLT_MAX, -FLT_MAX, -FLT_MAX, -FLT_MAX};
                int   ti[4] = {0x7fffffff, 0x7fffffff, 0x7fffffff, 0x7fffffff};
                for (int tile = lane; tile < NTILE_V; tile += 32) {
                    int base = r * NTILE_V + tile;
                    lsemerge(mx, se, __ldcg(&g_tm[base]), __ldcg(&g_ts[base]));
                    #pragma unroll
                    for (int j = 0; j < 4; j++)
                        ins4(__ldcg(&g_ttv[base * 4 + j]), __ldcg(&g_tti[base * 4 + j]), tv, ti);
                }
                #pragma unroll
                for (int off = 16; off > 0; off >>= 1) {
                    float om = __shfl_xor_sync(0xffffffff, mx, off);
                    float os = __shfl_xor_sync(0xffffffff, se, off);
                    lsemerge(mx, se, om, os);
                    merge_shfl(tv, ti, off);
                }
                if (lane == 0) {
                    float lse_r = mx + logf(se);
                    float base_sc = __ldcg(&g_scores[r]) - lse_r;
                    #pragma unroll
                    for (int j = 0; j < 4; j++) {
                        sm.cb.cv[k * 4 + j] = base_sc + tv[j];
                        sm.cb.ci[k * 4 + j] = k * V_ + ti[j];
                    }
                }
            }
            __syncthreads();
            if (tid == 0) {
                float tv[4] = {-FLT_MAX, -FLT_MAX, -FLT_MAX, -FLT_MAX};
                int   ti[4] = {0x7fffffff, 0x7fffffff, 0x7fffffff, 0x7fffffff};
                #pragma unroll
                for (int i = 0; i < 16; i++) ins4(sm.cb.cv[i], sm.cb.ci[i], tv, ti);
                #pragma unroll
                for (int j = 0; j < 4; j++) {
                    int id = ti[j];
                    int beam = id / V_;
                    int tok = id - beam * V_;
                    g_tokens[b * KB_ + j] = tok;
                    g_scores[b * KB_ + j] = tv[j];
                    g_tokh [t * BKr_ + b * KB_ + j] = tok;
                    g_beamh[t * BKr_ + b * KB_ + j] = beam;
                }
            }
        }
        gbar(eph);
    }

    // ---- backtrack + output
    if (bid == 0 && tid < 32) {
        int b = tid >> 2, k = tid & 3;
        int ptr = k;
        for (int t = T_ - 1; t >= 0; --t) {
            int tok = __ldcg(&g_tokh[t * BKr_ + b * KB_ + ptr]);
            int o = b * KB_ * T_ + k * T_ + t;
            if (o < out_size) out[o] = (float)tok;
            ptr = __ldcg(&g_beamh[t * BKr_ + b * KB_ + ptr]);
        }
        int o2 = B_ * KB_ * T_ + tid;
        if (o2 < out_size) out[o2] = __ldcg(&g_scores[tid]);
    }
}

// ================= encoder kernels (round-13, passing) =============================
__global__ void embed_enc_k(const int* X, const float* emb, const float* pos, float* h) {
    int r = blockIdx.x, tid = threadIdx.x;
    int tok = X[r];
    int s = r & (S_ - 1);
    #pragma unroll
    for (int i = 0; i < 3; i++) {
        int d = tid + i * 256;
        h[(size_t)r * D_ + d] = emb[(size_t)tok * D_ + d] + pos[(size_t)s * D_ + d];
    }
}

__global__ void mask_k(const int* X, float* mb) {
    int i = blockIdx.x * 256 + threadIdx.x;
    if (i < BS_) mb[i] = (X[i] != 0) ? 0.f : -1e9f;
}

__global__ void __launch_bounds__(256) sgemm128_k(
        const float* __restrict__ A, const float* __restrict__ Bm,
        float* __restrict__ C, int N, int K) {
    __shared__ __align__(16) float As[16][128];
    __shared__ __align__(16) float Bs[16][64];
    int tid = threadIdx.x;
    int tx = tid & 15, ty = tid >> 4;
    int mBase = blockIdx.y * 128, nBase = blockIdx.x * 64;
    float acc[8][4];
    #pragma unroll
    for (int i = 0; i < 8; i++)
        #pragma unroll
        for (int j = 0; j < 4; j++) acc[i][j] = 0.f;

    int am = tid >> 1, ak = (tid & 1) * 8;
    int b_k = tid >> 4, b_n = (tid & 15) * 4;

    for (int k0 = 0; k0 < K; k0 += 16) {
        float4 a0 = *(const float4*)&A[(size_t)(mBase + am) * K + k0 + ak];
        float4 a1 = *(const float4*)&A[(size_t)(mBase + am) * K + k0 + ak + 4];
        As[ak + 0][am] = a0.x; As[ak + 1][am] = a0.y;
        As[ak + 2][am] = a0.z; As[ak + 3][am] = a0.w;
        As[ak + 4][am] = a1.x; As[ak + 5][am] = a1.y;
        As[ak + 6][am] = a1.z; As[ak + 7][am] = a1.w;
        *(float4*)&Bs[b_k][b_n] = *(const float4*)&Bm[(size_t)(k0 + b_k) * N + nBase + b_n];
        __syncthreads();
        #pragma unroll
        for (int kk = 0; kk < 16; kk++) {
            float4 alo = *(const float4*)&As[kk][ty * 8];
            float4 ahi = *(const float4*)&As[kk][ty * 8 + 4];
            float4 b4  = *(const float4*)&Bs[kk][tx * 4];
            acc[0][0] += alo.x * b4.x; acc[0][1] += alo.x * b4.y; acc[0][2] += alo.x * b4.z; acc[0][3] += alo.x * b4.w;
            acc[1][0] += alo.y * b4.x; acc[1][1] += alo.y * b4.y; acc[1][2] += alo.y * b4.z; acc[1][3] += alo.y * b4.w;
            acc[2][0] += alo.z * b4.x; acc[2][1] += alo.z * b4.y; acc[2][2] += alo.z * b4.z; acc[2][3] += alo.z * b4.w;
            acc[3][0] += alo.w * b4.x; acc[3][1] += alo.w * b4.y; acc[3][2] += alo.w * b4.z; acc[3][3] += alo.w * b4.w;
            acc[4][0] += ahi.x * b4.x; acc[4][1] += ahi.x * b4.y; acc[4][2] += ahi.x * b4.z; acc[4][3] += ahi.x * b4.w;
            acc[5][0] += ahi.y * b4.x; acc[5][1] += ahi.y * b4.y; acc[5][2] += ahi.y * b4.z; acc[5][3] += ahi.y * b4.w;
            acc[6][0] += ahi.z * b4.x; acc[6][1] += ahi.z * b4.y; acc[6][2] += ahi.z * b4.z; acc[6][3] += ahi.z * b4.w;
            acc[7][0] += ahi.w * b4.x; acc[7][1] += ahi.w * b4.y; acc[7][2] += ahi.w * b4.z; acc[7][3] += ahi.w * b4.w;
        }
        __syncthreads();
    }
    #pragma unroll
    for (int i = 0; i < 8; i++) {
        int gm = mBase + ty * 8 + i;
        #pragma unroll
        for (int j = 0; j < 4; j++)
            C[(size_t)gm * N + nBase + tx * 4 + j] = acc[i][j];
    }
}

__global__ void eattn_k(const float* __restrict__ Q, const float* __restrict__ Km,
                        const float* __restrict__ Vm, const float* __restrict__ mb,
                        float* __restrict__ O) {
    __shared__ float Ks[64][64];
    __shared__ float Vs[64][64];
    int b = blockIdx.x / H_, h = blockIdx.x % H_;
    int tid = threadIdx.x;
    float q[64], acc[64];
    const float* qp = &Q[(size_t)(b * S_ + tid) * D_ + h * DH_];
    #pragma unroll
    for (int d = 0; d < 64; d++) { q[d] = qp[d] * 0.125f; acc[d] = 0.f; }
    float mrun = -3.0e38f, lrun = 0.f;

    for (int c0 = 0; c0 < S_; c0 += 64) {
        __syncthreads();
        #pragma unroll
        for (int i = 0; i < 32; i++) {
            int idx = tid + i * 128;
            int s = idx >> 6, d = idx & 63;
            Ks[s][d] = Km[(size_t)(b * S_ + c0 + s) * D_ + h * DH_ + d];
            Vs[s][d] = Vm[(size_t)(b * S_ + c0 + s) * D_ + h * DH_ + d];
        }
        __syncthreads();
        for (int j = 0; j < 64; j++) {
            float sc = mb[b * S_ + c0 + j];
            #pragma unroll
            for (int d = 0; d < 64; d++) sc += q[d] * Ks[j][d];
            float mnew = fmaxf(mrun, sc);
            float corr = expf(mrun - mnew);
            float p = expf(sc - mnew);
            lrun = lrun * corr + p;
            #pragma unroll
            for (int d = 0; d < 64; d++) acc[d] = acc[d] * corr + p * Vs[j][d];
            mrun = mnew;
        }
    }
    float inv = 1.f / lrun;
    float* op = &O[(size_t)(b * S_ + tid) * D_ + h * DH_];
    #pragma unroll
    for (int d = 0; d < 64; d++) op[d] = acc[d] * inv;
}

__global__ void addln_k(const float* __restrict__ a, const float* __restrict__ b,
                        float* __restrict__ o) {
    int r = blockIdx.x, tid = threadIdx.x;
    float v[3], s = 0.f, ss = 0.f;
    #pragma unroll
    for (int i = 0; i < 3; i++) {
        int d = tid + i * 256;
        v[i] = a[(size_t)r * D_ + d] + b[(size_t)r * D_ + d];
        s += v[i]; ss += v[i] * v[i];
    }
    __shared__ float sh1[8], sh2[8];
    __shared__ float s_mean, s_rstd;
    #pragma unroll
    for (int off = 16; off > 0; off >>= 1) {
        s  += __shfl_xor_sync(0xffffffff, s, off);
        ss += __shfl_xor_sync(0xffffffff, ss, off);
    }
    int w = tid >> 5;
    if ((tid & 31) == 0) { sh1[w] = s; sh2[w] = ss; }
    __syncthreads();
    if (tid == 0) {
        float ts = 0.f, tss = 0.f;
        #pragma unroll
        for (int i = 0; i < 8; i++) { ts += sh1[i]; tss += sh2[i]; }
        float m = ts / (float)D_;
        float var = tss / (float)D_ - m * m;
        s_mean = m; s_rstd = rsqrtf(var + 1e-5f);
    }
    __syncthreads();
    float m = s_mean, rs = s_rstd;
    #pragma unroll
    for (int i = 0; i < 3; i++) {
        int d = tid + i * 256;
        o[(size_t)r * D_ + d] = (v[i] - m) * rs;
    }
}

__global__ void gelu_k(float* x, int n) {
    int i = blockIdx.x * 256 + threadIdx.x;
    if (i < n) x[i] = gelu_f(x[i]);
}

// ================= host side ======================================================
extern "C" void kernel_launch(void* const* d_in, const int* in_sizes, int n_in,
                              void* d_out, int out_size) {
    const int*   X    = (const int*)  d_in[0];
    const float* emb  = (const float*)d_in[1];
    const float* pos  = (const float*)d_in[2];
    const float* Wq   = (const float*)d_in[3];
    const float* Wk   = (const float*)d_in[4];
    const float* Wv   = (const float*)d_in[5];
    const float* Wo   = (const float*)d_in[6];
    const float* W1   = (const float*)d_in[7];
    const float* W2   = (const float*)d_in[8];
    const float* Wdq  = (const float*)d_in[9];
    const float* Wdk  = (const float*)d_in[10];
    const float* Wdv  = (const float*)d_in[11];
    const float* Wdo  = (const float*)d_in[12];
    const float* Wd1  = (const float*)d_in[13];
    const float* Wd2  = (const float*)d_in[14];
    const float* Wvoc = (const float*)d_in[15];
    float* out = (float*)d_out;

    float *h, *t0, *t1, *t2, *ctx, *ffn, *Kmem, *Vmem, *mb;
    cudaGetSymbolAddress((void**)&h,    g_h);
    cudaGetSymbolAddress((void**)&t0,   g_t0);
    cudaGetSymbolAddress((void**)&t1,   g_t1);
    cudaGetSymbolAddress((void**)&t2,   g_t2);
    cudaGetSymbolAddress((void**)&ctx,  g_ctx);
    cudaGetSymbolAddress((void**)&ffn,  g_ffn);
    cudaGetSymbolAddress((void**)&Kmem, g_Kmem);
    cudaGetSymbolAddress((void**)&Vmem, g_Vmem);
    cudaGetSymbolAddress((void**)&mb,   g_mb);

    // ---------------- encoder (round-13) ----------------
    embed_enc_k<<<BS_, 256>>>(X, emb, pos, h);
    mask_k<<<4, 256>>>(X, mb);

    dim3 gD(D_ / 64, BS_ / 128);
    dim3 gF(DFF_ / 64, BS_ / 128);
    sgemm128_k<<<gD, 256>>>(h, Wq, t0, D_, D_);
    sgemm128_k<<<gD, 256>>>(h, Wk, t1, D_, D_);
    sgemm128_k<<<gD, 256>>>(h, Wv, t2, D_, D_);
    eattn_k<<<B_ * H_, 128>>>(t0, t1, t2, mb, ctx);
    sgemm128_k<<<gD, 256>>>(ctx, Wo, t0, D_, D_);
    addln_k<<<BS_, 256>>>(h, t0, h);
    sgemm128_k<<<gF, 256>>>(h, W1, ffn, DFF_, D_);
    gelu_k<<<(BS_ * DFF_) / 256, 256>>>(ffn, BS_ * DFF_);
    sgemm128_k<<<gD, 256>>>(ffn, W2, t0, D_, DFF_);
    addln_k<<<BS_, 256>>>(h, t0, h);
    sgemm128_k<<<gD, 256>>>(h, Wdk, Kmem, D_, D_);
    sgemm128_k<<<gD, 256>>>(h, Wdv, Vmem, D_, D_);

    // ---------------- decode: persistent megakernel (dynamic smem) ----------------
    static int smem_set = 0;
    int smemBytes = (int)sizeof(SmAll);
    if (!smem_set) {
        cudaFuncSetAttribute(decode_mega,
                             cudaFuncAttributeMaxDynamicSharedMemorySize, smemBytes);
        smem_set = 1;
    }
    decode_mega<<<GRID_, 256, smemBytes>>>(emb, pos, Wdq, Wdo, Wd1, Wd2, Wvoc,
                                           out, out_size);
}